// round 3
// baseline (speedup 1.0000x reference)
#include <cuda_runtime.h>
#include <cuda_bf16.h>

// Problem constants
#define BB  2
#define SS  2048
#define DD  1024
#define HH  16
#define HDD 64
#define MM  (BB*SS)        // 4096 rows

typedef unsigned long long u64;

// Packed f32x2 helpers (sm_100+): one issue slot = 2 fp32 FMAs.
__device__ __forceinline__ u64 pk2(float lo, float hi) {
    u64 r; asm("mov.b64 %0, {%1, %2};" : "=l"(r) : "f"(lo), "f"(hi)); return r;
}
__device__ __forceinline__ void upk2(float& lo, float& hi, u64 v) {
    asm("mov.b64 {%0, %1}, %2;" : "=f"(lo), "=f"(hi) : "l"(v));
}
__device__ __forceinline__ void fma2(u64& d, u64 a, u64 b) {
    asm("fma.rn.f32x2 %0, %1, %2, %3;" : "=l"(d) : "l"(a), "l"(b), "l"(d));
}
__device__ __forceinline__ void mul2(u64& d, u64 a, u64 b) {
    asm("mul.rn.f32x2 %0, %1, %2;" : "=l"(d) : "l"(a), "l"(b));
}

union F4 { float4 f4; float f[4]; u64 u2[2]; };

// Scratch (device globals; allocation-free rule)
__device__ float g_q [BB*HH*SS*HDD];   // [b,h,s,hd]
__device__ float g_k [BB*HH*SS*HDD];
__device__ float g_v [BB*HH*SS*HDD];
__device__ float g_pm[BB*HH*SS*HDD];   // causal prefix-mean of v
__device__ float g_am[BB*SS*DD];       // attention output, merged heads [b*s, d]

// ---------------------------------------------------------------------------
// Kernel 1: fused projection GEMM.  Y = X @ [qk_w | v_w] (+ qk_b on first 2D)
// M=4096, K=1024, N=3072.  128x128x8 tile, 256 threads, 8x8 per thread.
// FFMA2 inner loop; epilogue scatters into head-major q/k/v.
// ---------------------------------------------------------------------------
__global__ __launch_bounds__(256, 2)
void proj_gemm(const float* __restrict__ X,  const float* __restrict__ QKW,
               const float* __restrict__ QKB, const float* __restrict__ VW)
{
    __shared__ float As[8*128];   // As[k][m]
    __shared__ float Bs[8*128];   // Bs[k][n]
    const int m0 = blockIdx.y * 128;
    const int n0 = blockIdx.x * 128;

    const float* Bp; int ldb, bn0;
    if (n0 < 2048) { Bp = QKW; ldb = 2048; bn0 = n0; }
    else           { Bp = VW;  ldb = 1024; bn0 = n0 - 2048; }

    const int tid  = threadIdx.x;
    const int arow = tid >> 1,  akq = (tid & 1) * 4;
    const int brow = tid >> 5,  bnq = (tid & 31) * 4;
    const int ty   = tid >> 4,  tx  = tid & 15;

    u64 acc2[8][4] = {};   // 8 rows x 4 col-pairs

    float4 av = *(const float4*)&X [(m0 + arow) * 1024 + akq];
    float4 bv = *(const float4*)&Bp[brow * ldb + bn0 + bnq];

    for (int kt = 0; kt < 1024; kt += 8) {
        As[(akq+0)*128 + arow] = av.x;
        As[(akq+1)*128 + arow] = av.y;
        As[(akq+2)*128 + arow] = av.z;
        As[(akq+3)*128 + arow] = av.w;
        *(float4*)&Bs[brow * 128 + bnq] = bv;
        __syncthreads();
        if (kt + 8 < 1024) {
            av = *(const float4*)&X [(m0 + arow) * 1024 + kt + 8 + akq];
            bv = *(const float4*)&Bp[(kt + 8 + brow) * ldb + bn0 + bnq];
        }
        #pragma unroll
        for (int kk = 0; kk < 8; kk++) {
            F4 a0, a1, b0, b1;
            a0.f4 = *(float4*)&As[kk*128 + ty*8];
            a1.f4 = *(float4*)&As[kk*128 + ty*8 + 4];
            b0.f4 = *(float4*)&Bs[kk*128 + tx*8];
            b1.f4 = *(float4*)&Bs[kk*128 + tx*8 + 4];
            u64 b2[4] = { b0.u2[0], b0.u2[1], b1.u2[0], b1.u2[1] };
            #pragma unroll
            for (int i = 0; i < 8; i++) {
                float ai = (i < 4) ? a0.f[i] : a1.f[i-4];
                u64 ad = pk2(ai, ai);
                #pragma unroll
                for (int j = 0; j < 4; j++) fma2(acc2[i][j], ad, b2[j]);
            }
        }
        __syncthreads();
    }

    // Epilogue: add bias, scatter to head-major layouts.
    float bias[8];
    #pragma unroll
    for (int j = 0; j < 8; j++) {
        int nn = n0 + tx*8 + j;
        bias[j] = (nn < 2048) ? QKB[nn] : 0.f;
    }
    #pragma unroll
    for (int i = 0; i < 8; i++) {
        int mm = m0 + ty*8 + i;
        int bb = mm >> 11, ss = mm & 2047;
        float accr[8];
        #pragma unroll
        for (int j = 0; j < 4; j++) upk2(accr[2*j], accr[2*j+1], acc2[i][j]);
        #pragma unroll
        for (int j = 0; j < 8; j++) {
            int nn = n0 + tx*8 + j;
            float val = accr[j] + bias[j];
            float* dst; int col;
            if (nn < 1024)      { dst = g_q; col = nn; }
            else if (nn < 2048) { dst = g_k; col = nn - 1024; }
            else                { dst = g_v; col = nn - 2048; }
            int h = col >> 6, hd = col & 63;
            dst[(((bb << 4) + h) * 2048 + ss) * 64 + hd] = val;
        }
    }
}

// ---------------------------------------------------------------------------
// Kernel 2: causal prefix mean of v:  pm[s] = (1/(s+1)) * sum_{k<=s} v[k]
// One block per (b,h), 1024 threads = 16 chunks x 64 hd.
// ---------------------------------------------------------------------------
__global__ __launch_bounds__(1024)
void prefix_kernel()
{
    const int bh = blockIdx.x;
    const float* vp = g_v  + bh * SS * HDD;
    float*       pp = g_pm + bh * SS * HDD;
    const int tid = threadIdx.x;
    const int hd  = tid & 63;
    const int c   = tid >> 6;           // 0..15, chunk of 128 rows
    __shared__ float cs[16][64];

    const int s0 = c * 128;
    float acc = 0.f;
    #pragma unroll 4
    for (int i = 0; i < 128; i++) acc += vp[(s0 + i) * 64 + hd];
    cs[c][hd] = acc;
    __syncthreads();

    float off = 0.f;
    for (int cc = 0; cc < c; cc++) off += cs[cc][hd];

    float run = off;
    #pragma unroll 4
    for (int i = 0; i < 128; i++) {
        int s = s0 + i;
        run += vp[s * 64 + hd];
        pp[s * 64 + hd] = run / (float)(s + 1);
    }
}

// ---------------------------------------------------------------------------
// Kernel 3: flash attention + shaped epilogue.  FFMA2 inner loops.
// Block = (q-tile of 64) x (b,h).  256 threads, 4x4 register tiles.
// ---------------------------------------------------------------------------
#define ATTN_SMEM (3 * 64 * 64 * 4)

__global__ __launch_bounds__(256, 2)
void attn_kernel(const float* __restrict__ RG, const float* __restrict__ SG,
                 const float* __restrict__ CG)
{
    extern __shared__ float smf[];
    float* Qt = smf;                // Qt[hd][q]
    float* KP = smf + 64*64;        // Kt[hd][key]  then  Pt[key][q]
    float* Vs = smf + 2*64*64;      // Vs[key][hd]

    const int qt = blockIdx.x, bh = blockIdx.y;
    const int h  = bh & 15;
    const float* qp = g_q  + bh * SS * HDD;
    const float* kp = g_k  + bh * SS * HDD;
    const float* vp = g_v  + bh * SS * HDD;
    const float* pp = g_pm + bh * SS * HDD;

    const int tid = threadIdx.x;
    const int lr  = tid >> 4;           // 0..15 (load row group)
    const int lc  = (tid & 15) * 4;     // 0..60 (load col quad)
    const int ty  = tid >> 4, tx = tid & 15;
    const int ty4 = ty * 4, tx4 = tx * 4;
    const int q0  = qt * 64;

    // Load Q tile transposed (hd-major)
    #pragma unroll
    for (int rr = 0; rr < 4; rr++) {
        int row = rr * 16 + lr;
        float4 t = *(const float4*)&qp[(q0 + row) * 64 + lc];
        Qt[(lc+0)*64 + row] = t.x;
        Qt[(lc+1)*64 + row] = t.y;
        Qt[(lc+2)*64 + row] = t.z;
        Qt[(lc+3)*64 + row] = t.w;
    }

    u64 o2[4][2] = {};                  // 4 rows x 2 col-pairs
    float mrow[4], lrow[4];
    #pragma unroll
    for (int i = 0; i < 4; i++) { mrow[i] = -1e30f; lrow[i] = 0.f; }
    __syncthreads();

    const int nkv = qt + 1;
    for (int kv = 0; kv < nkv; kv++) {
        const int k0 = kv * 64;
        // Load K transposed + V natural
        #pragma unroll
        for (int rr = 0; rr < 4; rr++) {
            int row = rr * 16 + lr;
            float4 t = *(const float4*)&kp[(k0 + row) * 64 + lc];
            KP[(lc+0)*64 + row] = t.x;
            KP[(lc+1)*64 + row] = t.y;
            KP[(lc+2)*64 + row] = t.z;
            KP[(lc+3)*64 + row] = t.w;
            *(float4*)&Vs[row * 64 + lc] = *(const float4*)&vp[(k0 + row) * 64 + lc];
        }
        __syncthreads();

        // Scores: S = Q K^T  (reduce over hd), packed pairs along key dim
        u64 sv2[4][2] = {};
        #pragma unroll 8
        for (int kk = 0; kk < 64; kk++) {
            F4 a, b;
            a.f4 = *(float4*)&Qt[kk*64 + ty4];
            b.f4 = *(float4*)&KP[kk*64 + tx4];
            #pragma unroll
            for (int i = 0; i < 4; i++) {
                u64 ad = pk2(a.f[i], a.f[i]);
                fma2(sv2[i][0], ad, b.u2[0]);
                fma2(sv2[i][1], ad, b.u2[1]);
            }
        }

        // Online softmax (row state shared by the 16 lanes of each ty-group)
        const bool diag = (kv == nkv - 1);
        float p[4][4];
        #pragma unroll
        for (int i = 0; i < 4; i++) {
            float sv[4];
            upk2(sv[0], sv[1], sv2[i][0]);
            upk2(sv[2], sv[3], sv2[i][1]);
            const int qq = q0 + ty4 + i;
            float mt = -1e30f;
            #pragma unroll
            for (int j = 0; j < 4; j++) {
                float s = sv[j] * 0.125f;               // 1/sqrt(64)
                if (diag && (k0 + tx4 + j > qq)) s = -1e30f;
                sv[j] = s;
                mt = fmaxf(mt, s);
            }
            mt = fmaxf(mt, __shfl_xor_sync(0xffffffffu, mt, 1, 16));
            mt = fmaxf(mt, __shfl_xor_sync(0xffffffffu, mt, 2, 16));
            mt = fmaxf(mt, __shfl_xor_sync(0xffffffffu, mt, 4, 16));
            mt = fmaxf(mt, __shfl_xor_sync(0xffffffffu, mt, 8, 16));
            float mnew = fmaxf(mrow[i], mt);
            float corr = __expf(mrow[i] - mnew);
            mrow[i] = mnew;
            float ssum = 0.f;
            #pragma unroll
            for (int j = 0; j < 4; j++) {
                float pv = __expf(sv[j] - mnew);
                p[i][j] = pv;
                ssum += pv;
            }
            ssum += __shfl_xor_sync(0xffffffffu, ssum, 1, 16);
            ssum += __shfl_xor_sync(0xffffffffu, ssum, 2, 16);
            ssum += __shfl_xor_sync(0xffffffffu, ssum, 4, 16);
            ssum += __shfl_xor_sync(0xffffffffu, ssum, 8, 16);
            lrow[i] = lrow[i] * corr + ssum;
            u64 cpk = pk2(corr, corr);
            mul2(o2[i][0], o2[i][0], cpk);
            mul2(o2[i][1], o2[i][1], cpk);
        }

        __syncthreads();   // everyone done reading K before P overwrites KP
        // Store P transposed (key-major) into KP
        #pragma unroll
        for (int j = 0; j < 4; j++)
            *(float4*)&KP[(tx4 + j) * 64 + ty4] =
                make_float4(p[0][j], p[1][j], p[2][j], p[3][j]);
        __syncthreads();

        // O += P @ V  (reduce over key), packed pairs along hd dim
        #pragma unroll 8
        for (int kk = 0; kk < 64; kk++) {
            F4 a, b;
            a.f4 = *(float4*)&KP[kk*64 + ty4];
            b.f4 = *(float4*)&Vs[kk*64 + tx4];
            #pragma unroll
            for (int i = 0; i < 4; i++) {
                u64 ad = pk2(a.f[i], a.f[i]);
                fma2(o2[i][0], ad, b.u2[0]);
                fma2(o2[i][1], ad, b.u2[1]);
            }
        }
        __syncthreads();   // before next tile overwrites KP / Vs
    }

    // Shaped epilogue: rg*softmaxV + sg*v - cg*prefix_mean, merged-head store
    const float rgv = RG[h], sgv = SG[h], cgv = CG[h];
    const int bI = bh >> 4;
    #pragma unroll
    for (int i = 0; i < 4; i++) {
        const int qq = q0 + ty4 + i;
        const float inv = 1.f / lrow[i];
        float o[4];
        upk2(o[0], o[1], o2[i][0]);
        upk2(o[2], o[3], o2[i][1]);
        float4 vv  = *(const float4*)&vp[qq * 64 + tx4];
        float4 pm4 = *(const float4*)&pp[qq * 64 + tx4];
        float4 r;
        r.x = rgv * o[0] * inv + sgv * vv.x - cgv * pm4.x;
        r.y = rgv * o[1] * inv + sgv * vv.y - cgv * pm4.y;
        r.z = rgv * o[2] * inv + sgv * vv.z - cgv * pm4.z;
        r.w = rgv * o[3] * inv + sgv * vv.w - cgv * pm4.w;
        *(float4*)&g_am[(bI * SS + qq) * DD + h * 64 + tx4] = r;
    }
}

// ---------------------------------------------------------------------------
// Kernel 4: c_proj GEMM.  OUT = g_am @ W.  M=4096, K=1024, N=1024.  FFMA2.
// ---------------------------------------------------------------------------
__global__ __launch_bounds__(256, 2)
void out_gemm(const float* __restrict__ W, float* __restrict__ OUT)
{
    __shared__ float As[8*128];
    __shared__ float Bs[8*128];
    const int m0 = blockIdx.y * 128;
    const int n0 = blockIdx.x * 128;
    const int tid  = threadIdx.x;
    const int arow = tid >> 1,  akq = (tid & 1) * 4;
    const int brow = tid >> 5,  bnq = (tid & 31) * 4;
    const int ty   = tid >> 4,  tx  = tid & 15;

    u64 acc2[8][4] = {};

    float4 av = *(const float4*)&g_am[(m0 + arow) * 1024 + akq];
    float4 bv = *(const float4*)&W   [brow * 1024 + n0 + bnq];

    for (int kt = 0; kt < 1024; kt += 8) {
        As[(akq+0)*128 + arow] = av.x;
        As[(akq+1)*128 + arow] = av.y;
        As[(akq+2)*128 + arow] = av.z;
        As[(akq+3)*128 + arow] = av.w;
        *(float4*)&Bs[brow * 128 + bnq] = bv;
        __syncthreads();
        if (kt + 8 < 1024) {
            av = *(const float4*)&g_am[(m0 + arow) * 1024 + kt + 8 + akq];
            bv = *(const float4*)&W   [(kt + 8 + brow) * 1024 + n0 + bnq];
        }
        #pragma unroll
        for (int kk = 0; kk < 8; kk++) {
            F4 a0, a1, b0, b1;
            a0.f4 = *(float4*)&As[kk*128 + ty*8];
            a1.f4 = *(float4*)&As[kk*128 + ty*8 + 4];
            b0.f4 = *(float4*)&Bs[kk*128 + tx*8];
            b1.f4 = *(float4*)&Bs[kk*128 + tx*8 + 4];
            u64 b2[4] = { b0.u2[0], b0.u2[1], b1.u2[0], b1.u2[1] };
            #pragma unroll
            for (int i = 0; i < 8; i++) {
                float ai = (i < 4) ? a0.f[i] : a1.f[i-4];
                u64 ad = pk2(ai, ai);
                #pragma unroll
                for (int j = 0; j < 4; j++) fma2(acc2[i][j], ad, b2[j]);
            }
        }
        __syncthreads();
    }

    #pragma unroll
    for (int i = 0; i < 8; i++) {
        int mm = m0 + ty*8 + i;
        float accr[8];
        #pragma unroll
        for (int j = 0; j < 4; j++) upk2(accr[2*j], accr[2*j+1], acc2[i][j]);
        float* op = &OUT[mm * 1024 + n0 + tx*8];
        *(float4*)&op[0] = make_float4(accr[0], accr[1], accr[2], accr[3]);
        *(float4*)&op[4] = make_float4(accr[4], accr[5], accr[6], accr[7]);
    }
}

// ---------------------------------------------------------------------------
extern "C" void kernel_launch(void* const* d_in, const int* in_sizes, int n_in,
                              void* d_out, int out_size)
{
    (void)in_sizes; (void)n_in; (void)out_size;
    const float* x      = (const float*)d_in[0];
    const float* qk_w   = (const float*)d_in[1];
    const float* qk_b   = (const float*)d_in[2];
    const float* v_w    = (const float*)d_in[3];
    const float* cprojw = (const float*)d_in[4];
    const float* rg     = (const float*)d_in[5];
    const float* sg     = (const float*)d_in[6];
    const float* cg     = (const float*)d_in[7];

    proj_gemm<<<dim3(24, 32), 256>>>(x, qk_w, qk_b, v_w);
    prefix_kernel<<<BB * HH, 1024>>>();
    attn_kernel<<<dim3(SS / 64, BB * HH), 256, ATTN_SMEM>>>(rg, sg, cg);
    out_gemm<<<dim3(8, 32), 256>>>(cprojw, (float*)d_out);
}

// round 4
// speedup vs baseline: 1.2376x; 1.2376x over previous
#include <cuda_runtime.h>
#include <cuda_bf16.h>

// Problem constants
#define BB  2
#define SS  2048
#define DD  1024
#define HH  16
#define HDD 64

// Scratch (device globals; allocation-free rule)
// g_q, g_k are stored TRANSPOSED: [bh][hd][s]  (hd-major, for attention smem loads)
// g_v natural: [bh][s][hd]
__device__ float g_q [BB*HH*HDD*SS];
__device__ float g_k [BB*HH*HDD*SS];
__device__ float g_v [BB*HH*SS*HDD];
__device__ float g_pm[BB*HH*SS*HDD];   // causal prefix-mean of v (natural layout)
__device__ float g_am[BB*SS*DD];       // attention output, merged heads [b*s, d]

// ---------------------------------------------------------------------------
// Kernel 1: fused projection GEMM.  Y = X @ [qk_w | v_w] (+ qk_b on first 2D)
// M=4096, K=1024, N=3072.  128x128x8 tile, 256 threads, 8x8 per thread in
// split-quad mapping (rows ty*4 / 64+ty*4, cols tx*4 / 64+tx*4) so B-fragment
// LDS.128 are conflict-free and A-fragment LDS are broadcast.
// ---------------------------------------------------------------------------
__global__ __launch_bounds__(256, 2)
void proj_gemm(const float* __restrict__ X,  const float* __restrict__ QKW,
               const float* __restrict__ QKB, const float* __restrict__ VW)
{
    __shared__ float As[8*128];   // As[k][m]
    __shared__ float Bs[8*128];   // Bs[k][n]
    const int m0 = blockIdx.y * 128;
    const int n0 = blockIdx.x * 128;

    const float* Bp; int ldb, bn0;
    if (n0 < 2048) { Bp = QKW; ldb = 2048; bn0 = n0; }
    else           { Bp = VW;  ldb = 1024; bn0 = n0 - 2048; }

    const int tid  = threadIdx.x;
    const int arow = tid >> 1,  akq = (tid & 1) * 4;
    const int brow = tid >> 5,  bnq = (tid & 31) * 4;
    const int ty4  = (tid >> 4) * 4,  tx4 = (tid & 15) * 4;

    float acc[8][8];
    #pragma unroll
    for (int i = 0; i < 8; i++)
        #pragma unroll
        for (int j = 0; j < 8; j++) acc[i][j] = 0.f;

    float4 av = *(const float4*)&X [(m0 + arow) * 1024 + akq];
    float4 bv = *(const float4*)&Bp[brow * ldb + bn0 + bnq];

    for (int kt = 0; kt < 1024; kt += 8) {
        As[(akq+0)*128 + arow] = av.x;
        As[(akq+1)*128 + arow] = av.y;
        As[(akq+2)*128 + arow] = av.z;
        As[(akq+3)*128 + arow] = av.w;
        *(float4*)&Bs[brow * 128 + bnq] = bv;
        __syncthreads();
        if (kt + 8 < 1024) {
            av = *(const float4*)&X [(m0 + arow) * 1024 + kt + 8 + akq];
            bv = *(const float4*)&Bp[(kt + 8 + brow) * ldb + bn0 + bnq];
        }
        #pragma unroll
        for (int kk = 0; kk < 8; kk++) {
            float a[8], b[8];
            *(float4*)&a[0] = *(float4*)&As[kk*128 + ty4];
            *(float4*)&a[4] = *(float4*)&As[kk*128 + 64 + ty4];
            *(float4*)&b[0] = *(float4*)&Bs[kk*128 + tx4];
            *(float4*)&b[4] = *(float4*)&Bs[kk*128 + 64 + tx4];
            #pragma unroll
            for (int i = 0; i < 8; i++)
                #pragma unroll
                for (int j = 0; j < 8; j++)
                    acc[i][j] = fmaf(a[i], b[j], acc[i][j]);
        }
        __syncthreads();
    }

    // Epilogue: add bias; Q/K stored transposed [bh][hd][s], V natural.
    float bias[8];
    #pragma unroll
    for (int j = 0; j < 8; j++) {
        int nn = n0 + ((j < 4) ? tx4 + j : 64 + tx4 + j - 4);
        bias[j] = (nn < 2048) ? QKB[nn] : 0.f;
    }
    #pragma unroll
    for (int i = 0; i < 8; i++) {
        int mm = m0 + ((i < 4) ? ty4 + i : 64 + ty4 + i - 4);
        int bb = mm >> 11, ss = mm & 2047;
        #pragma unroll
        for (int j = 0; j < 8; j++) {
            int nn = n0 + ((j < 4) ? tx4 + j : 64 + tx4 + j - 4);
            float val = acc[i][j] + bias[j];
            if (nn < 1024) {
                int h = nn >> 6, hd = nn & 63;
                g_q[(((bb << 4) + h) * 64 + hd) * 2048 + ss] = val;
            } else if (nn < 2048) {
                int col = nn - 1024; int h = col >> 6, hd = col & 63;
                g_k[(((bb << 4) + h) * 64 + hd) * 2048 + ss] = val;
            } else {
                int col = nn - 2048; int h = col >> 6, hd = col & 63;
                g_v[(((bb << 4) + h) * 2048 + ss) * 64 + hd] = val;
            }
        }
    }
}

// ---------------------------------------------------------------------------
// Kernel 2: causal prefix mean of v:  pm[s] = (1/(s+1)) * sum_{k<=s} v[k]
// ---------------------------------------------------------------------------
__global__ __launch_bounds__(1024)
void prefix_kernel()
{
    const int bh = blockIdx.x;
    const float* vp = g_v  + bh * SS * HDD;
    float*       pp = g_pm + bh * SS * HDD;
    const int tid = threadIdx.x;
    const int hd  = tid & 63;
    const int c   = tid >> 6;           // 0..15, chunk of 128 rows
    __shared__ float cs[16][64];

    const int s0 = c * 128;
    float acc = 0.f;
    #pragma unroll 4
    for (int i = 0; i < 128; i++) acc += vp[(s0 + i) * 64 + hd];
    cs[c][hd] = acc;
    __syncthreads();

    float off = 0.f;
    for (int cc = 0; cc < c; cc++) off += cs[cc][hd];

    float run = off;
    #pragma unroll 4
    for (int i = 0; i < 128; i++) {
        int s = s0 + i;
        run += vp[s * 64 + hd];
        pp[s * 64 + hd] = run / (float)(s + 1);
    }
}

// ---------------------------------------------------------------------------
// Kernel 3: flash attention + shaped epilogue.
// Q/K read from transposed gmem -> straight smem copies, no transpose stores.
// Qt[hd][q] reads are broadcast; Kt[hd][k] reads conflict-free; P stored
// natural [q][k] (conflict-free STS.128, broadcast float4 reads in PV).
// smem 48KB: Qt 16K | KP 16K (Kt then Ps) | Vs 16K.
// ---------------------------------------------------------------------------
#define ATTN_SMEM (3 * 64 * 64 * 4)

__global__ __launch_bounds__(256, 2)
void attn_kernel(const float* __restrict__ RG, const float* __restrict__ SG,
                 const float* __restrict__ CG)
{
    extern __shared__ float smf[];
    float* Qt = smf;                // Qt[hd][q]
    float* KP = smf + 64*64;        // Kt[hd][k]  then  Ps[q][k]
    float* Vs = smf + 2*64*64;      // Vs[k][hd]

    const int qt = (gridDim.x - 1) - blockIdx.x;   // big tiles first
    const int bh = blockIdx.y;
    const int h  = bh & 15;
    const float* qTp = g_q  + bh * HDD * SS;   // [hd][s]
    const float* kTp = g_k  + bh * HDD * SS;   // [hd][s]
    const float* vp  = g_v  + bh * SS * HDD;   // [s][hd]
    const float* pp  = g_pm + bh * SS * HDD;

    const int tid = threadIdx.x;
    const int ty4 = (tid >> 4) * 4, tx4 = (tid & 15) * 4;
    const int q0  = qt * 64;

    // Load Q tile (straight copy, already hd-major in gmem)
    #pragma unroll
    for (int r = 0; r < 4; r++) {
        int idx = r * 256 + tid;                 // 0..1023
        int hd = idx >> 4, c = (idx & 15) * 4;
        *(float4*)&Qt[hd * 64 + c] = *(const float4*)&qTp[hd * 2048 + q0 + c];
    }

    float o[4][4] = {};
    float mrow[4], lrow[4];
    #pragma unroll
    for (int i = 0; i < 4; i++) { mrow[i] = -1e30f; lrow[i] = 0.f; }
    __syncthreads();

    const int nkv = qt + 1;
    for (int kv = 0; kv < nkv; kv++) {
        const int k0 = kv * 64;
        // Load Kt (straight) + V (natural)
        #pragma unroll
        for (int r = 0; r < 4; r++) {
            int idx = r * 256 + tid;
            int row = idx >> 4, c = (idx & 15) * 4;
            *(float4*)&KP[row * 64 + c] = *(const float4*)&kTp[row * 2048 + k0 + c];
            *(float4*)&Vs[row * 64 + c] = *(const float4*)&vp[(k0 + row) * 64 + c];
        }
        __syncthreads();

        // Scores: S = Q K^T (reduce over hd); a broadcast, b conflict-free
        float sv[4][4] = {};
        #pragma unroll 8
        for (int kk = 0; kk < 64; kk++) {
            float4 a4 = *(float4*)&Qt[kk*64 + ty4];
            float4 b4 = *(float4*)&KP[kk*64 + tx4];
            float a[4] = {a4.x, a4.y, a4.z, a4.w};
            float b[4] = {b4.x, b4.y, b4.z, b4.w};
            #pragma unroll
            for (int i = 0; i < 4; i++)
                #pragma unroll
                for (int j = 0; j < 4; j++)
                    sv[i][j] = fmaf(a[i], b[j], sv[i][j]);
        }

        // Online softmax (row state shared by 16 lanes of each ty-group)
        const bool diag = (kv == nkv - 1);
        float p[4][4];
        #pragma unroll
        for (int i = 0; i < 4; i++) {
            const int qq = q0 + ty4 + i;
            float mt = -1e30f;
            #pragma unroll
            for (int j = 0; j < 4; j++) {
                float s = sv[i][j] * 0.125f;            // 1/sqrt(64)
                if (diag && (k0 + tx4 + j > qq)) s = -1e30f;
                sv[i][j] = s;
                mt = fmaxf(mt, s);
            }
            mt = fmaxf(mt, __shfl_xor_sync(0xffffffffu, mt, 1, 16));
            mt = fmaxf(mt, __shfl_xor_sync(0xffffffffu, mt, 2, 16));
            mt = fmaxf(mt, __shfl_xor_sync(0xffffffffu, mt, 4, 16));
            mt = fmaxf(mt, __shfl_xor_sync(0xffffffffu, mt, 8, 16));
            float mnew = fmaxf(mrow[i], mt);
            float corr = __expf(mrow[i] - mnew);
            mrow[i] = mnew;
            float ssum = 0.f;
            #pragma unroll
            for (int j = 0; j < 4; j++) {
                float pv = __expf(sv[i][j] - mnew);
                p[i][j] = pv;
                ssum += pv;
            }
            ssum += __shfl_xor_sync(0xffffffffu, ssum, 1, 16);
            ssum += __shfl_xor_sync(0xffffffffu, ssum, 2, 16);
            ssum += __shfl_xor_sync(0xffffffffu, ssum, 4, 16);
            ssum += __shfl_xor_sync(0xffffffffu, ssum, 8, 16);
            lrow[i] = lrow[i] * corr + ssum;
            #pragma unroll
            for (int j = 0; j < 4; j++) o[i][j] *= corr;
        }

        __syncthreads();   // everyone done reading Kt before Ps overwrites it
        // Store P natural [q][k]: conflict-free STS.128
        #pragma unroll
        for (int i = 0; i < 4; i++)
            *(float4*)&KP[(ty4 + i) * 64 + tx4] =
                make_float4(p[i][0], p[i][1], p[i][2], p[i][3]);
        __syncwarp();      // P rows are warp-private (same ty-group)

        // O += P @ V (reduce over key): p broadcast float4 per 4 keys
        #pragma unroll 4
        for (int kk4 = 0; kk4 < 16; kk4++) {
            float4 pr[4];
            #pragma unroll
            for (int i = 0; i < 4; i++)
                pr[i] = *(float4*)&KP[(ty4 + i) * 64 + kk4 * 4];
            #pragma unroll
            for (int t = 0; t < 4; t++) {
                float4 v4 = *(float4*)&Vs[(kk4 * 4 + t) * 64 + tx4];
                float vb[4] = {v4.x, v4.y, v4.z, v4.w};
                float pa[4] = { t==0?pr[0].x: t==1?pr[0].y: t==2?pr[0].z: pr[0].w,
                                t==0?pr[1].x: t==1?pr[1].y: t==2?pr[1].z: pr[1].w,
                                t==0?pr[2].x: t==1?pr[2].y: t==2?pr[2].z: pr[2].w,
                                t==0?pr[3].x: t==1?pr[3].y: t==2?pr[3].z: pr[3].w };
                #pragma unroll
                for (int i = 0; i < 4; i++)
                    #pragma unroll
                    for (int j = 0; j < 4; j++)
                        o[i][j] = fmaf(pa[i], vb[j], o[i][j]);
            }
        }
        __syncthreads();   // before next tile overwrites Kt / Vs
    }

    // Shaped epilogue: rg*softmaxV + sg*v - cg*prefix_mean, merged-head store
    const float rgv = RG[h], sgv = SG[h], cgv = CG[h];
    const int bI = bh >> 4;
    #pragma unroll
    for (int i = 0; i < 4; i++) {
        const int qq = q0 + ty4 + i;
        const float inv = 1.f / lrow[i];
        float4 vv  = *(const float4*)&vp[qq * 64 + tx4];
        float4 pm4 = *(const float4*)&pp[qq * 64 + tx4];
        float4 r;
        r.x = rgv * o[i][0] * inv + sgv * vv.x - cgv * pm4.x;
        r.y = rgv * o[i][1] * inv + sgv * vv.y - cgv * pm4.y;
        r.z = rgv * o[i][2] * inv + sgv * vv.z - cgv * pm4.z;
        r.w = rgv * o[i][3] * inv + sgv * vv.w - cgv * pm4.w;
        *(float4*)&g_am[(bI * SS + qq) * DD + h * 64 + tx4] = r;
    }
}

// ---------------------------------------------------------------------------
// Kernel 4: c_proj GEMM.  OUT = g_am @ W.  M=4096, K=1024, N=1024.
// Same split-quad conflict-free mapping as proj_gemm.
// ---------------------------------------------------------------------------
__global__ __launch_bounds__(256, 2)
void out_gemm(const float* __restrict__ W, float* __restrict__ OUT)
{
    __shared__ float As[8*128];
    __shared__ float Bs[8*128];
    const int m0 = blockIdx.y * 128;
    const int n0 = blockIdx.x * 128;
    const int tid  = threadIdx.x;
    const int arow = tid >> 1,  akq = (tid & 1) * 4;
    const int brow = tid >> 5,  bnq = (tid & 31) * 4;
    const int ty4  = (tid >> 4) * 4,  tx4 = (tid & 15) * 4;

    float acc[8][8];
    #pragma unroll
    for (int i = 0; i < 8; i++)
        #pragma unroll
        for (int j = 0; j < 8; j++) acc[i][j] = 0.f;

    float4 av = *(const float4*)&g_am[(m0 + arow) * 1024 + akq];
    float4 bv = *(const float4*)&W   [brow * 1024 + n0 + bnq];

    for (int kt = 0; kt < 1024; kt += 8) {
        As[(akq+0)*128 + arow] = av.x;
        As[(akq+1)*128 + arow] = av.y;
        As[(akq+2)*128 + arow] = av.z;
        As[(akq+3)*128 + arow] = av.w;
        *(float4*)&Bs[brow * 128 + bnq] = bv;
        __syncthreads();
        if (kt + 8 < 1024) {
            av = *(const float4*)&g_am[(m0 + arow) * 1024 + kt + 8 + akq];
            bv = *(const float4*)&W   [(kt + 8 + brow) * 1024 + n0 + bnq];
        }
        #pragma unroll
        for (int kk = 0; kk < 8; kk++) {
            float a[8], b[8];
            *(float4*)&a[0] = *(float4*)&As[kk*128 + ty4];
            *(float4*)&a[4] = *(float4*)&As[kk*128 + 64 + ty4];
            *(float4*)&b[0] = *(float4*)&Bs[kk*128 + tx4];
            *(float4*)&b[4] = *(float4*)&Bs[kk*128 + 64 + tx4];
            #pragma unroll
            for (int i = 0; i < 8; i++)
                #pragma unroll
                for (int j = 0; j < 8; j++)
                    acc[i][j] = fmaf(a[i], b[j], acc[i][j]);
        }
        __syncthreads();
    }

    #pragma unroll
    for (int i = 0; i < 8; i++) {
        int mm = m0 + ((i < 4) ? ty4 + i : 64 + ty4 + i - 4);
        float* op = &OUT[mm * 1024 + n0];
        *(float4*)&op[tx4]      = make_float4(acc[i][0], acc[i][1], acc[i][2], acc[i][3]);
        *(float4*)&op[64 + tx4] = make_float4(acc[i][4], acc[i][5], acc[i][6], acc[i][7]);
    }
}

// ---------------------------------------------------------------------------
extern "C" void kernel_launch(void* const* d_in, const int* in_sizes, int n_in,
                              void* d_out, int out_size)
{
    (void)in_sizes; (void)n_in; (void)out_size;
    const float* x      = (const float*)d_in[0];
    const float* qk_w   = (const float*)d_in[1];
    const float* qk_b   = (const float*)d_in[2];
    const float* v_w    = (const float*)d_in[3];
    const float* cprojw = (const float*)d_in[4];
    const float* rg     = (const float*)d_in[5];
    const float* sg     = (const float*)d_in[6];
    const float* cg     = (const float*)d_in[7];

    proj_gemm<<<dim3(24, 32), 256>>>(x, qk_w, qk_b, v_w);
    prefix_kernel<<<BB * HH, 1024>>>();
    attn_kernel<<<dim3(SS / 64, BB * HH), 256, ATTN_SMEM>>>(rg, sg, cg);
    out_gemm<<<dim3(8, 32), 256>>>(cprojw, (float*)d_out);
}

// round 6
// speedup vs baseline: 1.6106x; 1.3013x over previous
#include <cuda_runtime.h>
#include <cuda_bf16.h>
#include <cstdint>

// Problem constants
#define BB  2
#define SS  2048
#define DD  1024
#define HH  16
#define HDD 64

// ---------------------------------------------------------------------------
// Scratch (device globals; allocation-free rule)
// ---------------------------------------------------------------------------
__device__ float g_q [BB*HH*HDD*SS];   // transposed [bh][hd][s]
__device__ float g_k [BB*HH*HDD*SS];   // transposed [bh][hd][s]
__device__ float g_v [BB*HH*SS*HDD];   // natural [bh][s][hd]
__device__ float g_pm[BB*HH*SS*HDD];   // causal prefix-mean of v
__device__ float g_am[BB*SS*DD];       // attention out, merged heads [b*s][d]

// bf16 hi/lo operand images
__device__ __nv_bfloat16 g_XA_hi[4096*1024];   // x, row-major [4096][1024]
__device__ __nv_bfloat16 g_XA_lo[4096*1024];
__device__ __nv_bfloat16 g_AM_hi[4096*1024];   // g_am, row-major
__device__ __nv_bfloat16 g_AM_lo[4096*1024];
__device__ __nv_bfloat16 g_WB_hi[3072*1024];   // [n][k]: rows 0..2047 qk_w^T, 2048.. v_w^T
__device__ __nv_bfloat16 g_WB_lo[3072*1024];
__device__ __nv_bfloat16 g_WC_hi[1024*1024];   // cproj^T [n][k]
__device__ __nv_bfloat16 g_WC_lo[1024*1024];

typedef unsigned long long u64;

__device__ __forceinline__ uint32_t smem_u32(const void* p) {
    uint32_t a;
    asm("{ .reg .u64 t; cvta.to.shared.u64 t, %1; cvt.u32.u64 %0, t; }"
        : "=r"(a) : "l"(p));
    return a;
}

#define CP16(dst, src) \
    asm volatile("cp.async.cg.shared.global [%0], [%1], 16;" \
                 :: "r"(dst), "l"(src) : "memory")
#define CP_COMMIT() asm volatile("cp.async.commit_group;" ::: "memory")
#define CP_WAIT0()  asm volatile("cp.async.wait_group 0;" ::: "memory")

#define LDMX4(r, addr) \
    asm volatile("ldmatrix.sync.aligned.m8n8.x4.shared.b16 {%0,%1,%2,%3}, [%4];" \
                 : "=r"((r)[0]), "=r"((r)[1]), "=r"((r)[2]), "=r"((r)[3]) : "r"(addr))

#define MMA_BF16(d, a, b) \
    asm volatile("mma.sync.aligned.m16n8k16.row.col.f32.bf16.bf16.f32 " \
                 "{%0,%1,%2,%3}, {%4,%5,%6,%7}, {%8,%9}, {%0,%1,%2,%3};" \
                 : "+f"((d)[0]), "+f"((d)[1]), "+f"((d)[2]), "+f"((d)[3]) \
                 : "r"((a)[0]), "r"((a)[1]), "r"((a)[2]), "r"((a)[3]), \
                   "r"((b)[0]), "r"((b)[1]))

// ---------------------------------------------------------------------------
// Conversion: fp32 row-major [4096][1024] -> bf16 hi/lo row-major.
// which=0: src=x -> g_XA;  which=1: src=g_am -> g_AM.
// ---------------------------------------------------------------------------
__global__ __launch_bounds__(256)
void convert_A(const float* __restrict__ src, int which)
{
    const float* s = which ? (const float*)g_am : src;
    size_t base = ((size_t)blockIdx.x * 256 + threadIdx.x) * 8;
    float4 a = *(const float4*)(s + base);
    float4 b = *(const float4*)(s + base + 4);
    float xs[8] = {a.x, a.y, a.z, a.w, b.x, b.y, b.z, b.w};
    union { __nv_bfloat16 h[8]; uint4 u; } ph, pl;
    #pragma unroll
    for (int i = 0; i < 8; i++) {
        __nv_bfloat16 hb = __float2bfloat16(xs[i]);
        ph.h[i] = hb;
        pl.h[i] = __float2bfloat16(xs[i] - __bfloat162float(hb));
    }
    __nv_bfloat16* hi = which ? g_AM_hi : g_XA_hi;
    __nv_bfloat16* lo = which ? g_AM_lo : g_XA_lo;
    *(uint4*)(hi + base) = ph.u;
    *(uint4*)(lo + base) = pl.u;
}

// ---------------------------------------------------------------------------
// Conversion + transpose: W [1024][N] fp32 -> [n][k] bf16 hi/lo at row offset.
// which=0 -> g_WB, which=1 -> g_WC.  Block 256 = 32x8, 32x32 tile.
// ---------------------------------------------------------------------------
__global__ __launch_bounds__(256)
void convert_W(const float* __restrict__ W, int N, int which, int roff)
{
    __shared__ float t[32][33];
    const int n0 = blockIdx.x * 32, k0 = blockIdx.y * 32;
    const int tx = threadIdx.x & 31, ty = threadIdx.x >> 5;
    #pragma unroll
    for (int i = 0; i < 4; i++)
        t[ty + 8*i][tx] = W[(size_t)(k0 + ty + 8*i) * N + n0 + tx];
    __syncthreads();
    __nv_bfloat16* dh = which ? g_WC_hi : g_WB_hi;
    __nv_bfloat16* dl = which ? g_WC_lo : g_WB_lo;
    #pragma unroll
    for (int i = 0; i < 4; i++) {
        float x = t[tx][ty + 8*i];
        __nv_bfloat16 hb = __float2bfloat16(x);
        size_t off = (size_t)(roff + n0 + ty + 8*i) * 1024 + k0 + tx;
        dh[off] = hb;
        dl[off] = __float2bfloat16(x - __bfloat162float(hb));
    }
}

// ---------------------------------------------------------------------------
// mma.sync bf16-split GEMM.  C = Ah*Bh + Ah*Bl + Al*Bh (fp32 accum).
// Block 128x128, K=1024 in 32-wide chunks, cp.async double buffer.
// 8 warps = 4(M) x 2(N); warp tile 32x64 = 2x8 m16n8k16 frags.
// smem stage: Ah|Al|Bh|Bl, each 128 rows x 80B (32 bf16 data + pad) = 10240B.
// mode 0: proj (B = g_WB, N=3072; scatter q/k transposed + v natural, bias)
// mode 1: c_proj (B = g_WC; plain store to OUT)
// ---------------------------------------------------------------------------
#define SMEM_STAGE 40960
#define SMEM_GEMM  (2 * SMEM_STAGE)

__global__ __launch_bounds__(256, 1)
void mma_gemm(int mode, const float* __restrict__ QKB, float* __restrict__ OUT)
{
    extern __shared__ char smc[];
    const uint32_t sbase = smem_u32(smc);
    const int tid = threadIdx.x, lane = tid & 31, wid = tid >> 5;
    const int nt = blockIdx.x, mt = blockIdx.y;
    const int m0 = mt * 128, n0 = nt * 128;
    const int warpM = wid & 3, warpN = wid >> 2;

    const __nv_bfloat16 *Ah, *Al, *Bh, *Bl;
    if (mode == 0) { Ah = g_XA_hi; Al = g_XA_lo; Bh = g_WB_hi; Bl = g_WB_lo; }
    else           { Ah = g_AM_hi; Al = g_AM_lo; Bh = g_WC_hi; Bl = g_WC_lo; }

    float c[16][4];
    #pragma unroll
    for (int i = 0; i < 16; i++)
        #pragma unroll
        for (int j = 0; j < 4; j++) c[i][j] = 0.f;

    // per-thread load map: 2048 16B chunks per stage, 8 per thread
    auto load_stage = [&](int it, int buf) {
        const uint32_t st = sbase + buf * SMEM_STAGE;
        const int k0 = it * 32;
        #pragma unroll
        for (int cc = 0; cc < 8; cc++) {
            int id  = cc * 256 + tid;
            int arr = id >> 9, rem = id & 511, row = rem >> 2, kq = rem & 3;
            const __nv_bfloat16* g = (arr == 0) ? Ah : (arr == 1) ? Al
                                   : (arr == 2) ? Bh : Bl;
            int grow = (arr < 2) ? (m0 + row) : (n0 + row);
            const void* src = g + (size_t)grow * 1024 + k0 + kq * 8;
            uint32_t dst = st + arr * 10240 + row * 80 + kq * 16;
            CP16(dst, src);
        }
        CP_COMMIT();
    };

    load_stage(0, 0);
    for (int it = 0; it < 32; it++) {
        CP_WAIT0();
        __syncthreads();
        if (it + 1 < 32) load_stage(it + 1, (it + 1) & 1);
        const uint32_t st = sbase + (it & 1) * SMEM_STAGE;

        const int matq = lane >> 3, r8 = lane & 7;
        #pragma unroll
        for (int kh = 0; kh < 2; kh++) {
            uint32_t ah[2][4], al[2][4];
            const int arow = ((matq & 1) << 3) + r8;
            const int akof = (((matq >> 1) << 3) + kh * 16) * 2;
            #pragma unroll
            for (int mt2 = 0; mt2 < 2; mt2++) {
                int row = warpM * 32 + mt2 * 16 + arow;
                uint32_t ad = st + row * 80 + akof;
                LDMX4(ah[mt2], ad);
                LDMX4(al[mt2], ad + 10240);
            }
            uint32_t bhf[8][2], blf[8][2];
            const int brow = ((matq >> 1) << 3) + r8;
            const int bkof = (((matq & 1) << 3) + kh * 16) * 2;
            #pragma unroll
            for (int p = 0; p < 4; p++) {
                int row = warpN * 64 + p * 16 + brow;
                uint32_t bd = st + 2 * 10240 + row * 80 + bkof;
                uint32_t t4[4];
                LDMX4(t4, bd);
                bhf[p*2][0] = t4[0]; bhf[p*2][1] = t4[1];
                bhf[p*2+1][0] = t4[2]; bhf[p*2+1][1] = t4[3];
                LDMX4(t4, bd + 10240);
                blf[p*2][0] = t4[0]; blf[p*2][1] = t4[1];
                blf[p*2+1][0] = t4[2]; blf[p*2+1][1] = t4[3];
            }
            // 3 split terms, C-frag reuse distance = 16 mma
            #pragma unroll
            for (int mt2 = 0; mt2 < 2; mt2++)
                #pragma unroll
                for (int n2 = 0; n2 < 8; n2++)
                    MMA_BF16(c[mt2*8+n2], ah[mt2], bhf[n2]);
            #pragma unroll
            for (int mt2 = 0; mt2 < 2; mt2++)
                #pragma unroll
                for (int n2 = 0; n2 < 8; n2++)
                    MMA_BF16(c[mt2*8+n2], ah[mt2], blf[n2]);
            #pragma unroll
            for (int mt2 = 0; mt2 < 2; mt2++)
                #pragma unroll
                for (int n2 = 0; n2 < 8; n2++)
                    MMA_BF16(c[mt2*8+n2], al[mt2], bhf[n2]);
        }
        __syncthreads();
    }

    // Epilogue
    if (mode == 1) {
        #pragma unroll
        for (int mt2 = 0; mt2 < 2; mt2++)
            #pragma unroll
            for (int n2 = 0; n2 < 8; n2++) {
                float* f = c[mt2*8+n2];
                int r0 = m0 + warpM * 32 + mt2 * 16 + (lane >> 2);
                int cb = n0 + warpN * 64 + n2 * 8 + (lane & 3) * 2;
                *(float2*)&OUT[(size_t)r0 * 1024 + cb]       = make_float2(f[0], f[1]);
                *(float2*)&OUT[(size_t)(r0 + 8) * 1024 + cb] = make_float2(f[2], f[3]);
            }
    } else {
        #pragma unroll
        for (int mt2 = 0; mt2 < 2; mt2++)
            #pragma unroll
            for (int n2 = 0; n2 < 8; n2++) {
                float* f = c[mt2*8+n2];
                int r0 = m0 + warpM * 32 + mt2 * 16 + (lane >> 2);
                int cb = n0 + warpN * 64 + n2 * 8 + (lane & 3) * 2;
                #pragma unroll
                for (int e = 0; e < 4; e++) {
                    int mm = r0 + (e >> 1) * 8;
                    int n  = cb + (e & 1);
                    float val = f[(e >> 1) * 2 + (e & 1)];
                    int bb = mm >> 11, ss = mm & 2047;
                    if (n < 2048) {
                        float v = val + QKB[n];
                        int colg = n & 1023;
                        float* dst = (n < 1024) ? g_q : g_k;
                        dst[(((size_t)(bb * 16 + (colg >> 6))) * 64 + (colg & 63)) * 2048 + ss] = v;
                    } else {
                        int colg = n - 2048;
                        g_v[(((size_t)(bb * 16 + (colg >> 6))) * 2048 + ss) * 64 + (colg & 63)] = val;
                    }
                }
            }
    }
}

// ---------------------------------------------------------------------------
// Kernel: causal prefix mean of v (unchanged from R4)
// ---------------------------------------------------------------------------
__global__ __launch_bounds__(1024)
void prefix_kernel()
{
    const int bh = blockIdx.x;
    const float* vp = g_v  + bh * SS * HDD;
    float*       pp = g_pm + bh * SS * HDD;
    const int tid = threadIdx.x;
    const int hd  = tid & 63;
    const int c   = tid >> 6;
    __shared__ float cs[16][64];

    const int s0 = c * 128;
    float acc = 0.f;
    #pragma unroll 4
    for (int i = 0; i < 128; i++) acc += vp[(s0 + i) * 64 + hd];
    cs[c][hd] = acc;
    __syncthreads();

    float off = 0.f;
    for (int cc = 0; cc < c; cc++) off += cs[cc][hd];

    float run = off;
    #pragma unroll 4
    for (int i = 0; i < 128; i++) {
        int s = s0 + i;
        run += vp[s * 64 + hd];
        pp[s * 64 + hd] = run / (float)(s + 1);
    }
}

// ---------------------------------------------------------------------------
// Kernel: flash attention + shaped epilogue (unchanged from R4)
// ---------------------------------------------------------------------------
#define ATTN_SMEM (3 * 64 * 64 * 4)

__global__ __launch_bounds__(256, 2)
void attn_kernel(const float* __restrict__ RG, const float* __restrict__ SG,
                 const float* __restrict__ CG)
{
    extern __shared__ float smf[];
    float* Qt = smf;                // Qt[hd][q]
    float* KP = smf + 64*64;        // Kt[hd][k]  then  Ps[q][k]
    float* Vs = smf + 2*64*64;      // Vs[k][hd]

    const int qt = (gridDim.x - 1) - blockIdx.x;
    const int bh = blockIdx.y;
    const int h  = bh & 15;
    const float* qTp = g_q  + bh * HDD * SS;
    const float* kTp = g_k  + bh * HDD * SS;
    const float* vp  = g_v  + bh * SS * HDD;
    const float* pp  = g_pm + bh * SS * HDD;

    const int tid = threadIdx.x;
    const int ty4 = (tid >> 4) * 4, tx4 = (tid & 15) * 4;
    const int q0  = qt * 64;

    #pragma unroll
    for (int r = 0; r < 4; r++) {
        int idx = r * 256 + tid;
        int hd = idx >> 4, c = (idx & 15) * 4;
        *(float4*)&Qt[hd * 64 + c] = *(const float4*)&qTp[hd * 2048 + q0 + c];
    }

    float o[4][4] = {};
    float mrow[4], lrow[4];
    #pragma unroll
    for (int i = 0; i < 4; i++) { mrow[i] = -1e30f; lrow[i] = 0.f; }
    __syncthreads();

    const int nkv = qt + 1;
    for (int kv = 0; kv < nkv; kv++) {
        const int k0 = kv * 64;
        #pragma unroll
        for (int r = 0; r < 4; r++) {
            int idx = r * 256 + tid;
            int row = idx >> 4, c = (idx & 15) * 4;
            *(float4*)&KP[row * 64 + c] = *(const float4*)&kTp[row * 2048 + k0 + c];
            *(float4*)&Vs[row * 64 + c] = *(const float4*)&vp[(k0 + row) * 64 + c];
        }
        __syncthreads();

        float sv[4][4] = {};
        #pragma unroll 8
        for (int kk = 0; kk < 64; kk++) {
            float4 a4 = *(float4*)&Qt[kk*64 + ty4];
            float4 b4 = *(float4*)&KP[kk*64 + tx4];
            float a[4] = {a4.x, a4.y, a4.z, a4.w};
            float b[4] = {b4.x, b4.y, b4.z, b4.w};
            #pragma unroll
            for (int i = 0; i < 4; i++)
                #pragma unroll
                for (int j = 0; j < 4; j++)
                    sv[i][j] = fmaf(a[i], b[j], sv[i][j]);
        }

        const bool diag = (kv == nkv - 1);
        float p[4][4];
        #pragma unroll
        for (int i = 0; i < 4; i++) {
            const int qq = q0 + ty4 + i;
            float mt2 = -1e30f;
            #pragma unroll
            for (int j = 0; j < 4; j++) {
                float s = sv[i][j] * 0.125f;
                if (diag && (k0 + tx4 + j > qq)) s = -1e30f;
                sv[i][j] = s;
                mt2 = fmaxf(mt2, s);
            }
            mt2 = fmaxf(mt2, __shfl_xor_sync(0xffffffffu, mt2, 1, 16));
            mt2 = fmaxf(mt2, __shfl_xor_sync(0xffffffffu, mt2, 2, 16));
            mt2 = fmaxf(mt2, __shfl_xor_sync(0xffffffffu, mt2, 4, 16));
            mt2 = fmaxf(mt2, __shfl_xor_sync(0xffffffffu, mt2, 8, 16));
            float mnew = fmaxf(mrow[i], mt2);
            float corr = __expf(mrow[i] - mnew);
            mrow[i] = mnew;
            float ssum = 0.f;
            #pragma unroll
            for (int j = 0; j < 4; j++) {
                float pv = __expf(sv[i][j] - mnew);
                p[i][j] = pv;
                ssum += pv;
            }
            ssum += __shfl_xor_sync(0xffffffffu, ssum, 1, 16);
            ssum += __shfl_xor_sync(0xffffffffu, ssum, 2, 16);
            ssum += __shfl_xor_sync(0xffffffffu, ssum, 4, 16);
            ssum += __shfl_xor_sync(0xffffffffu, ssum, 8, 16);
            lrow[i] = lrow[i] * corr + ssum;
            #pragma unroll
            for (int j = 0; j < 4; j++) o[i][j] *= corr;
        }

        __syncthreads();
        #pragma unroll
        for (int i = 0; i < 4; i++)
            *(float4*)&KP[(ty4 + i) * 64 + tx4] =
                make_float4(p[i][0], p[i][1], p[i][2], p[i][3]);
        __syncwarp();

        #pragma unroll 4
        for (int kk4 = 0; kk4 < 16; kk4++) {
            float4 pr[4];
            #pragma unroll
            for (int i = 0; i < 4; i++)
                pr[i] = *(float4*)&KP[(ty4 + i) * 64 + kk4 * 4];
            #pragma unroll
            for (int t = 0; t < 4; t++) {
                float4 v4 = *(float4*)&Vs[(kk4 * 4 + t) * 64 + tx4];
                float vb[4] = {v4.x, v4.y, v4.z, v4.w};
                float pa[4] = { t==0?pr[0].x: t==1?pr[0].y: t==2?pr[0].z: pr[0].w,
                                t==0?pr[1].x: t==1?pr[1].y: t==2?pr[1].z: pr[1].w,
                                t==0?pr[2].x: t==1?pr[2].y: t==2?pr[2].z: pr[2].w,
                                t==0?pr[3].x: t==1?pr[3].y: t==2?pr[3].z: pr[3].w };
                #pragma unroll
                for (int i = 0; i < 4; i++)
                    #pragma unroll
                    for (int j = 0; j < 4; j++)
                        o[i][j] = fmaf(pa[i], vb[j], o[i][j]);
            }
        }
        __syncthreads();
    }

    const float rgv = RG[h], sgv = SG[h], cgv = CG[h];
    const int bI = bh >> 4;
    #pragma unroll
    for (int i = 0; i < 4; i++) {
        const int qq = q0 + ty4 + i;
        const float inv = 1.f / lrow[i];
        float4 vv  = *(const float4*)&vp[qq * 64 + tx4];
        float4 pm4 = *(const float4*)&pp[qq * 64 + tx4];
        float4 r;
        r.x = rgv * o[i][0] * inv + sgv * vv.x - cgv * pm4.x;
        r.y = rgv * o[i][1] * inv + sgv * vv.y - cgv * pm4.y;
        r.z = rgv * o[i][2] * inv + sgv * vv.z - cgv * pm4.z;
        r.w = rgv * o[i][3] * inv + sgv * vv.w - cgv * pm4.w;
        *(float4*)&g_am[(bI * SS + qq) * DD + h * 64 + tx4] = r;
    }
}

// ---------------------------------------------------------------------------
extern "C" void kernel_launch(void* const* d_in, const int* in_sizes, int n_in,
                              void* d_out, int out_size)
{
    (void)in_sizes; (void)n_in; (void)out_size;
    const float* x      = (const float*)d_in[0];
    const float* qk_w   = (const float*)d_in[1];
    const float* qk_b   = (const float*)d_in[2];
    const float* v_w    = (const float*)d_in[3];
    const float* cprojw = (const float*)d_in[4];
    const float* rg     = (const float*)d_in[5];
    const float* sg     = (const float*)d_in[6];
    const float* cg     = (const float*)d_in[7];

    cudaFuncSetAttribute(mma_gemm, cudaFuncAttributeMaxDynamicSharedMemorySize, SMEM_GEMM);

    convert_A<<<2048, 256>>>(x, 0);
    convert_W<<<dim3(64, 32), 256>>>(qk_w,   2048, 0, 0);
    convert_W<<<dim3(32, 32), 256>>>(v_w,    1024, 0, 2048);
    convert_W<<<dim3(32, 32), 256>>>(cprojw, 1024, 1, 0);
    mma_gemm<<<dim3(24, 32), 256, SMEM_GEMM>>>(0, qk_b, nullptr);
    prefix_kernel<<<BB * HH, 1024>>>();
    attn_kernel<<<dim3(SS / 64, BB * HH), 256, ATTN_SMEM>>>(rg, sg, cg);
    convert_A<<<2048, 256>>>(nullptr, 1);
    mma_gemm<<<dim3(8, 32), 256, SMEM_GEMM>>>(1, nullptr, (float*)d_out);
}

// round 7
// speedup vs baseline: 2.4575x; 1.5259x over previous
#include <cuda_runtime.h>
#include <cuda_bf16.h>
#include <cstdint>

// Problem constants
#define BB  2
#define SS  2048
#define DD  1024
#define HH  16
#define HDD 64

typedef unsigned long long u64;

// ---------------------------------------------------------------------------
// Scratch (device globals; allocation-free rule)
// ---------------------------------------------------------------------------
__device__ float g_v [BB*HH*SS*HDD];   // fp32 natural [bh][s][hd]
__device__ float g_pm[BB*HH*SS*HDD];   // causal prefix-mean of v

// bf16 hi/lo operands
__device__ __nv_bfloat16 g_Qh[BB*HH*SS*HDD];   // [bh][s][hd]
__device__ __nv_bfloat16 g_Ql[BB*HH*SS*HDD];
__device__ __nv_bfloat16 g_Kh[BB*HH*SS*HDD];   // [bh][s][hd]
__device__ __nv_bfloat16 g_Kl[BB*HH*SS*HDD];
__device__ __nv_bfloat16 g_VTh[BB*HH*HDD*SS];  // [bh][hd][s]
__device__ __nv_bfloat16 g_VTl[BB*HH*HDD*SS];

__device__ __nv_bfloat16 g_XA_hi[4096*1024];   // x row-major
__device__ __nv_bfloat16 g_XA_lo[4096*1024];
__device__ __nv_bfloat16 g_AM_hi[4096*1024];   // attention out (written by attn)
__device__ __nv_bfloat16 g_AM_lo[4096*1024];
__device__ __nv_bfloat16 g_WB_hi[3072*1024];   // [n][k]: 0..2047 qk_w^T, 2048.. v_w^T
__device__ __nv_bfloat16 g_WB_lo[3072*1024];
__device__ __nv_bfloat16 g_WC_hi[1024*1024];   // cproj^T [n][k]
__device__ __nv_bfloat16 g_WC_lo[1024*1024];

// ---------------------------------------------------------------------------
// PTX helpers
// ---------------------------------------------------------------------------
__device__ __forceinline__ uint32_t smem_u32(const void* p) {
    uint32_t a;
    asm("{ .reg .u64 t; cvta.to.shared.u64 t, %1; cvt.u32.u64 %0, t; }"
        : "=r"(a) : "l"(p));
    return a;
}

#define CP16(dst, src) \
    asm volatile("cp.async.cg.shared.global [%0], [%1], 16;" \
                 :: "r"(dst), "l"(src) : "memory")
#define CP_COMMIT() asm volatile("cp.async.commit_group;" ::: "memory")
#define CP_WAIT0()  asm volatile("cp.async.wait_group 0;" ::: "memory")

#define LDMX4(r, addr) \
    asm volatile("ldmatrix.sync.aligned.m8n8.x4.shared.b16 {%0,%1,%2,%3}, [%4];" \
                 : "=r"((r)[0]), "=r"((r)[1]), "=r"((r)[2]), "=r"((r)[3]) : "r"(addr))

#define MMA_BF16(d, a, b) \
    asm volatile("mma.sync.aligned.m16n8k16.row.col.f32.bf16.bf16.f32 " \
                 "{%0,%1,%2,%3}, {%4,%5,%6,%7}, {%8,%9}, {%0,%1,%2,%3};" \
                 : "+f"((d)[0]), "+f"((d)[1]), "+f"((d)[2]), "+f"((d)[3]) \
                 : "r"((a)[0]), "r"((a)[1]), "r"((a)[2]), "r"((a)[3]), \
                   "r"((b)[0]), "r"((b)[1]))

// Split fp32 pair -> bf16 hi pair + lo pair (packed, v0 in low half)
__device__ __forceinline__ void split2(float v0, float v1, uint32_t& hp, uint32_t& lp) {
    asm("cvt.rn.bf16x2.f32 %0, %1, %2;" : "=r"(hp) : "f"(v1), "f"(v0));
    float h0 = __int_as_float(hp << 16);
    float h1 = __int_as_float(hp & 0xFFFF0000u);
    float l0 = v0 - h0, l1 = v1 - h1;
    asm("cvt.rn.bf16x2.f32 %0, %1, %2;" : "=r"(lp) : "f"(l1), "f"(l0));
}

// Fast exp2 (t <= 0), FMA/ALU pipes only, ~2e-6 rel err.
__device__ __forceinline__ float exp2p(float t) {
    t = fmaxf(t, -126.f);
    float z  = t + 12582912.f;          // round-to-nearest integer trick
    float nf = z - 12582912.f;
    float f  = t - nf;
    float p  = 1.3333558146e-3f;
    p = fmaf(p, f, 9.6181291076e-3f);
    p = fmaf(p, f, 5.5504108665e-2f);
    p = fmaf(p, f, 2.4022650696e-1f);
    p = fmaf(p, f, 6.9314718056e-1f);
    p = fmaf(p, f, 1.0f);
    int ib = __float_as_int(z) << 23;   // == n<<23 (mod 2^32)
    return __int_as_float(__float_as_int(p) + ib);
}

// ---------------------------------------------------------------------------
// convert_A: x fp32 [4096][1024] -> g_XA hi/lo
// ---------------------------------------------------------------------------
__global__ __launch_bounds__(256)
void convert_A(const float* __restrict__ src)
{
    size_t base = ((size_t)blockIdx.x * 256 + threadIdx.x) * 8;
    float4 a = *(const float4*)(src + base);
    float4 b = *(const float4*)(src + base + 4);
    float xs[8] = {a.x, a.y, a.z, a.w, b.x, b.y, b.z, b.w};
    union { __nv_bfloat16 h[8]; uint4 u; } ph, pl;
    #pragma unroll
    for (int i = 0; i < 8; i++) {
        __nv_bfloat16 hb = __float2bfloat16(xs[i]);
        ph.h[i] = hb;
        pl.h[i] = __float2bfloat16(xs[i] - __bfloat162float(hb));
    }
    *(uint4*)(g_XA_hi + base) = ph.u;
    *(uint4*)(g_XA_lo + base) = pl.u;
}

// ---------------------------------------------------------------------------
// convert_W: W [1024][N] fp32 -> [n][k] bf16 hi/lo at row offset (transpose)
// ---------------------------------------------------------------------------
__global__ __launch_bounds__(256)
void convert_W(const float* __restrict__ W, int N, int which, int roff)
{
    __shared__ float t[32][33];
    const int n0 = blockIdx.x * 32, k0 = blockIdx.y * 32;
    const int tx = threadIdx.x & 31, ty = threadIdx.x >> 5;
    #pragma unroll
    for (int i = 0; i < 4; i++)
        t[ty + 8*i][tx] = W[(size_t)(k0 + ty + 8*i) * N + n0 + tx];
    __syncthreads();
    __nv_bfloat16* dh = which ? g_WC_hi : g_WB_hi;
    __nv_bfloat16* dl = which ? g_WC_lo : g_WB_lo;
    #pragma unroll
    for (int i = 0; i < 4; i++) {
        float x = t[tx][ty + 8*i];
        __nv_bfloat16 hb = __float2bfloat16(x);
        size_t off = (size_t)(roff + n0 + ty + 8*i) * 1024 + k0 + tx;
        dh[off] = hb;
        dl[off] = __float2bfloat16(x - __bfloat162float(hb));
    }
}

// ---------------------------------------------------------------------------
// convert_VT: g_v [bh][s][hd] fp32 -> g_VT hi/lo [bh][hd][s] bf16
// ---------------------------------------------------------------------------
__global__ __launch_bounds__(256)
void convert_VT()
{
    __shared__ float tb[32][65];
    const int bh = blockIdx.y, s0 = blockIdx.x * 32;
    const int tid = threadIdx.x;
    {
        int r = tid >> 3, c8 = (tid & 7) * 8;
        const float* vp = g_v + ((size_t)bh * 2048 + s0 + r) * 64 + c8;
        float4 a = *(const float4*)vp, b = *(const float4*)(vp + 4);
        tb[r][c8+0]=a.x; tb[r][c8+1]=a.y; tb[r][c8+2]=a.z; tb[r][c8+3]=a.w;
        tb[r][c8+4]=b.x; tb[r][c8+5]=b.y; tb[r][c8+6]=b.z; tb[r][c8+7]=b.w;
    }
    __syncthreads();
    int hd = tid >> 2, sg = (tid & 3) * 8;
    union { __nv_bfloat16 h[8]; uint4 u; } ph, pl;
    #pragma unroll
    for (int i = 0; i < 8; i++) {
        float x = tb[sg + i][hd];
        __nv_bfloat16 hb = __float2bfloat16(x);
        ph.h[i] = hb;
        pl.h[i] = __float2bfloat16(x - __bfloat162float(hb));
    }
    size_t off = ((size_t)bh * 64 + hd) * 2048 + s0 + sg;
    *(uint4*)(g_VTh + off) = ph.u;
    *(uint4*)(g_VTl + off) = pl.u;
}

// ---------------------------------------------------------------------------
// mma.sync bf16-split GEMM (structure identical to R6, mode-0 epilogue new)
// ---------------------------------------------------------------------------
#define SMEM_STAGE 40960
#define SMEM_GEMM  (2 * SMEM_STAGE)

__global__ __launch_bounds__(256, 1)
void mma_gemm(int mode, const float* __restrict__ QKB, float* __restrict__ OUT)
{
    extern __shared__ char smc[];
    const uint32_t sbase = smem_u32(smc);
    const int tid = threadIdx.x, lane = tid & 31, wid = tid >> 5;
    const int nt = blockIdx.x, mt = blockIdx.y;
    const int m0 = mt * 128, n0 = nt * 128;
    const int warpM = wid & 3, warpN = wid >> 2;

    const __nv_bfloat16 *Ah, *Al, *Bh, *Bl;
    if (mode == 0) { Ah = g_XA_hi; Al = g_XA_lo; Bh = g_WB_hi; Bl = g_WB_lo; }
    else           { Ah = g_AM_hi; Al = g_AM_lo; Bh = g_WC_hi; Bl = g_WC_lo; }

    float c[16][4];
    #pragma unroll
    for (int i = 0; i < 16; i++)
        #pragma unroll
        for (int j = 0; j < 4; j++) c[i][j] = 0.f;

    auto load_stage = [&](int it, int buf) {
        const uint32_t st = sbase + buf * SMEM_STAGE;
        const int k0 = it * 32;
        #pragma unroll
        for (int cc = 0; cc < 8; cc++) {
            int id  = cc * 256 + tid;
            int arr = id >> 9, rem = id & 511, row = rem >> 2, kq = rem & 3;
            const __nv_bfloat16* g = (arr == 0) ? Ah : (arr == 1) ? Al
                                   : (arr == 2) ? Bh : Bl;
            int grow = (arr < 2) ? (m0 + row) : (n0 + row);
            const void* src = g + (size_t)grow * 1024 + k0 + kq * 8;
            uint32_t dst = st + arr * 10240 + row * 80 + kq * 16;
            CP16(dst, src);
        }
        CP_COMMIT();
    };

    load_stage(0, 0);
    for (int it = 0; it < 32; it++) {
        CP_WAIT0();
        __syncthreads();
        if (it + 1 < 32) load_stage(it + 1, (it + 1) & 1);
        const uint32_t st = sbase + (it & 1) * SMEM_STAGE;

        const int matq = lane >> 3, r8 = lane & 7;
        #pragma unroll
        for (int kh = 0; kh < 2; kh++) {
            uint32_t ah[2][4], al[2][4];
            const int arow = ((matq & 1) << 3) + r8;
            const int akof = (((matq >> 1) << 3) + kh * 16) * 2;
            #pragma unroll
            for (int mt2 = 0; mt2 < 2; mt2++) {
                int row = warpM * 32 + mt2 * 16 + arow;
                uint32_t ad = st + row * 80 + akof;
                LDMX4(ah[mt2], ad);
                LDMX4(al[mt2], ad + 10240);
            }
            uint32_t bhf[8][2], blf[8][2];
            const int brow = ((matq >> 1) << 3) + r8;
            const int bkof = (((matq & 1) << 3) + kh * 16) * 2;
            #pragma unroll
            for (int p = 0; p < 4; p++) {
                int row = warpN * 64 + p * 16 + brow;
                uint32_t bd = st + 2 * 10240 + row * 80 + bkof;
                uint32_t t4[4];
                LDMX4(t4, bd);
                bhf[p*2][0] = t4[0]; bhf[p*2][1] = t4[1];
                bhf[p*2+1][0] = t4[2]; bhf[p*2+1][1] = t4[3];
                LDMX4(t4, bd + 10240);
                blf[p*2][0] = t4[0]; blf[p*2][1] = t4[1];
                blf[p*2+1][0] = t4[2]; blf[p*2+1][1] = t4[3];
            }
            #pragma unroll
            for (int mt2 = 0; mt2 < 2; mt2++)
                #pragma unroll
                for (int n2 = 0; n2 < 8; n2++)
                    MMA_BF16(c[mt2*8+n2], ah[mt2], bhf[n2]);
            #pragma unroll
            for (int mt2 = 0; mt2 < 2; mt2++)
                #pragma unroll
                for (int n2 = 0; n2 < 8; n2++)
                    MMA_BF16(c[mt2*8+n2], ah[mt2], blf[n2]);
            #pragma unroll
            for (int mt2 = 0; mt2 < 2; mt2++)
                #pragma unroll
                for (int n2 = 0; n2 < 8; n2++)
                    MMA_BF16(c[mt2*8+n2], al[mt2], bhf[n2]);
        }
        __syncthreads();
    }

    if (mode == 1) {
        #pragma unroll
        for (int mt2 = 0; mt2 < 2; mt2++)
            #pragma unroll
            for (int n2 = 0; n2 < 8; n2++) {
                float* f = c[mt2*8+n2];
                int r0 = m0 + warpM * 32 + mt2 * 16 + (lane >> 2);
                int cb = n0 + warpN * 64 + n2 * 8 + (lane & 3) * 2;
                *(float2*)&OUT[(size_t)r0 * 1024 + cb]       = make_float2(f[0], f[1]);
                *(float2*)&OUT[(size_t)(r0 + 8) * 1024 + cb] = make_float2(f[2], f[3]);
            }
    } else {
        #pragma unroll
        for (int mt2 = 0; mt2 < 2; mt2++)
            #pragma unroll
            for (int n2 = 0; n2 < 8; n2++) {
                float* f = c[mt2*8+n2];
                int r0 = m0 + warpM * 32 + mt2 * 16 + (lane >> 2);
                int cb = n0 + warpN * 64 + n2 * 8 + (lane & 3) * 2;
                #pragma unroll
                for (int rr = 0; rr < 2; rr++) {
                    int mm = r0 + rr * 8;
                    int bb = mm >> 11, ss = mm & 2047;
                    float v0 = f[rr*2], v1 = f[rr*2+1];
                    if (cb < 2048) {
                        v0 += QKB[cb]; v1 += QKB[cb+1];
                        int colg = cb & 1023, hh = colg >> 6, hd = colg & 63;
                        size_t off = ((size_t)(bb * 16 + hh) * 2048 + ss) * 64 + hd;
                        uint32_t hp, lp; split2(v0, v1, hp, lp);
                        if (cb < 1024) { *(uint32_t*)(g_Qh + off) = hp;
                                         *(uint32_t*)(g_Ql + off) = lp; }
                        else           { *(uint32_t*)(g_Kh + off) = hp;
                                         *(uint32_t*)(g_Kl + off) = lp; }
                    } else {
                        int colg = cb - 2048, hh = colg >> 6, hd = colg & 63;
                        *(float2*)&g_v[((size_t)(bb * 16 + hh) * 2048 + ss) * 64 + hd] =
                            make_float2(v0, v1);
                    }
                }
            }
    }
}

// ---------------------------------------------------------------------------
// prefix mean of v (unchanged)
// ---------------------------------------------------------------------------
__global__ __launch_bounds__(1024)
void prefix_kernel()
{
    const int bh = blockIdx.x;
    const float* vp = g_v  + (size_t)bh * SS * HDD;
    float*       pp = g_pm + (size_t)bh * SS * HDD;
    const int tid = threadIdx.x;
    const int hd  = tid & 63;
    const int c   = tid >> 6;
    __shared__ float cs[16][64];

    const int s0 = c * 128;
    float acc = 0.f;
    #pragma unroll 4
    for (int i = 0; i < 128; i++) acc += vp[(s0 + i) * 64 + hd];
    cs[c][hd] = acc;
    __syncthreads();

    float off = 0.f;
    for (int cc = 0; cc < c; cc++) off += cs[cc][hd];

    float run = off;
    #pragma unroll 4
    for (int i = 0; i < 128; i++) {
        int s = s0 + i;
        run += vp[s * 64 + hd];
        pp[s * 64 + hd] = run / (float)(s + 1);
    }
}

// ---------------------------------------------------------------------------
// Flash attention on mma.sync (bf16 hi/lo split) + shaped epilogue.
// Block: 128 q x (bh).  8 warps, 16 q-rows per warp.  kv tiles of 64.
// smem: two 36864B stages (Kh|Kl|VTh|VTl, 64 rows x 144B each);
//       Q staged once in stage0 region before the kv loop.
// ---------------------------------------------------------------------------
#define ROWB 144
#define OPB  (64 * ROWB)      // 9216
#define STAGEB (4 * OPB)      // 36864
#define ATTN_SMEM2 (2 * STAGEB)

__global__ __launch_bounds__(256, 1)
void attn_mma(const float* __restrict__ RG, const float* __restrict__ SG,
              const float* __restrict__ CG)
{
    extern __shared__ char smc[];
    const uint32_t sb = smem_u32(smc);
    const int tid = threadIdx.x, lane = tid & 31, w = tid >> 5;
    const int qt = (gridDim.x - 1) - blockIdx.x;
    const int bh = blockIdx.y, h = bh & 15;
    const int q0 = qt * 128;

    const __nv_bfloat16* Qh = g_Qh + (size_t)bh * 2048 * 64;
    const __nv_bfloat16* Ql = g_Ql + (size_t)bh * 2048 * 64;
    const __nv_bfloat16* Kh = g_Kh + (size_t)bh * 2048 * 64;
    const __nv_bfloat16* Kl = g_Kl + (size_t)bh * 2048 * 64;
    const __nv_bfloat16* VTh = g_VTh + (size_t)bh * 64 * 2048;
    const __nv_bfloat16* VTl = g_VTl + (size_t)bh * 64 * 2048;

    // ---- stage Q (128 rows x 128B, hi then lo) into stage0 region ----
    #pragma unroll
    for (int cc = 0; cc < 8; cc++) {
        int id = cc * 256 + tid;            // 0..2047
        int half = id >> 10;
        int rem = id & 1023, row = rem >> 3, kq = rem & 7;
        const __nv_bfloat16* src = (half ? Ql : Qh) + (size_t)(q0 + row) * 64 + kq * 8;
        CP16(sb + half * 18432 + row * ROWB + kq * 16, src);
    }
    CP_COMMIT(); CP_WAIT0();
    __syncthreads();

    // ---- extract persistent Q A-frags (4 ksteps, hi/lo) ----
    const int matq = lane >> 3, r8 = lane & 7;
    const int arow = ((matq & 1) << 3) + r8;
    const int akb  = ((matq >> 1) << 3);
    uint32_t qfh[4][4], qfl[4][4];
    #pragma unroll
    for (int ks = 0; ks < 4; ks++) {
        uint32_t ad = sb + (16 * w + arow) * ROWB + (akb + ks * 16) * 2;
        LDMX4(qfh[ks], ad);
        LDMX4(qfl[ks], ad + 18432);
    }
    __syncthreads();   // Q staging free before KV loads overwrite it

    float o[8][4];
    #pragma unroll
    for (int j = 0; j < 8; j++)
        #pragma unroll
        for (int e = 0; e < 4; e++) o[j][e] = 0.f;
    float mrow[2] = { -1e30f, -1e30f }, lrow[2] = { 0.f, 0.f };

    const int ntiles = 2 * qt + 2;
    const int brow = ((matq >> 1) << 3) + r8;
    const int bkb  = ((matq & 1) << 3);
    const int g = lane >> 2, t2 = (lane & 3) * 2;
    const float cexp = 0.125f * 1.44269504f;

    auto load_kv = [&](int t, int buf) {
        const uint32_t st = sb + buf * STAGEB;
        const int k0 = t * 64;
        #pragma unroll
        for (int cc = 0; cc < 8; cc++) {
            int id = cc * 256 + tid;
            int arr = id >> 9, rem = id & 511, row = rem >> 3, kq = rem & 7;
            const __nv_bfloat16* gp;
            size_t goff;
            if (arr < 2) { gp = arr ? Kl : Kh; goff = (size_t)(k0 + row) * 64 + kq * 8; }
            else { gp = (arr == 2) ? VTh : VTl; goff = (size_t)row * 2048 + k0 + kq * 8; }
            CP16(st + arr * OPB + row * ROWB + kq * 16, gp + goff);
        }
        CP_COMMIT();
    };

    load_kv(0, 0);
    for (int t = 0; t < ntiles; t++) {
        CP_WAIT0();
        __syncthreads();
        if (t + 1 < ntiles) load_kv(t + 1, (t + 1) & 1);
        const uint32_t st = sb + (t & 1) * STAGEB;
        const int k0 = t * 64;
        const bool active = (k0 <= q0 + 16 * w + 15);

        if (active) {
            // ---- S = Q K^T (3 split terms) ----
            float s[8][4];
            #pragma unroll
            for (int j = 0; j < 8; j++)
                #pragma unroll
                for (int e = 0; e < 4; e++) s[j][e] = 0.f;

            #pragma unroll
            for (int ks = 0; ks < 4; ks++) {
                uint32_t bhf[8][2], blf[8][2];
                #pragma unroll
                for (int p = 0; p < 4; p++) {
                    uint32_t bd = st + (p * 16 + brow) * ROWB + (bkb + ks * 16) * 2;
                    uint32_t t4[4];
                    LDMX4(t4, bd);
                    bhf[p*2][0] = t4[0]; bhf[p*2][1] = t4[1];
                    bhf[p*2+1][0] = t4[2]; bhf[p*2+1][1] = t4[3];
                    LDMX4(t4, bd + OPB);
                    blf[p*2][0] = t4[0]; blf[p*2][1] = t4[1];
                    blf[p*2+1][0] = t4[2]; blf[p*2+1][1] = t4[3];
                }
                #pragma unroll
                for (int j = 0; j < 8; j++) MMA_BF16(s[j], qfh[ks], bhf[j]);
                #pragma unroll
                for (int j = 0; j < 8; j++) MMA_BF16(s[j], qfl[ks], bhf[j]);
                #pragma unroll
                for (int j = 0; j < 8; j++) MMA_BF16(s[j], qfh[ks], blf[j]);
            }

            // ---- causal mask ----
            const int qrow0 = q0 + 16 * w + g;
            if (k0 + 63 > q0 + 16 * w) {
                #pragma unroll
                for (int j = 0; j < 8; j++) {
                    int kc = k0 + 8 * j + t2;
                    if (kc     > qrow0)     s[j][0] = -1e30f;
                    if (kc + 1 > qrow0)     s[j][1] = -1e30f;
                    if (kc     > qrow0 + 8) s[j][2] = -1e30f;
                    if (kc + 1 > qrow0 + 8) s[j][3] = -1e30f;
                }
            }

            // ---- online softmax ----
            float mx0 = -1e30f, mx1 = -1e30f;
            #pragma unroll
            for (int j = 0; j < 8; j++) {
                mx0 = fmaxf(mx0, fmaxf(s[j][0], s[j][1]));
                mx1 = fmaxf(mx1, fmaxf(s[j][2], s[j][3]));
            }
            mx0 = fmaxf(mx0, __shfl_xor_sync(0xffffffffu, mx0, 1));
            mx0 = fmaxf(mx0, __shfl_xor_sync(0xffffffffu, mx0, 2));
            mx1 = fmaxf(mx1, __shfl_xor_sync(0xffffffffu, mx1, 1));
            mx1 = fmaxf(mx1, __shfl_xor_sync(0xffffffffu, mx1, 2));
            float mn0 = fmaxf(mrow[0], mx0), mn1 = fmaxf(mrow[1], mx1);
            float corr0 = exp2p((mrow[0] - mn0) * cexp);
            float corr1 = exp2p((mrow[1] - mn1) * cexp);
            mrow[0] = mn0; mrow[1] = mn1;
            float nm0 = -mn0 * cexp, nm1 = -mn1 * cexp;

            float sum0 = 0.f, sum1 = 0.f;
            uint32_t pah[4][4], pal[4][4];
            #pragma unroll
            for (int j = 0; j < 8; j++) {
                float p0 = exp2p(fmaf(s[j][0], cexp, nm0));
                float p1 = exp2p(fmaf(s[j][1], cexp, nm0));
                float p2 = exp2p(fmaf(s[j][2], cexp, nm1));
                float p3 = exp2p(fmaf(s[j][3], cexp, nm1));
                sum0 += p0 + p1; sum1 += p2 + p3;
                uint32_t h01, l01, h23, l23;
                split2(p0, p1, h01, l01);
                split2(p2, p3, h23, l23);
                pah[j >> 1][(j & 1) * 2 + 0] = h01;
                pah[j >> 1][(j & 1) * 2 + 1] = h23;
                pal[j >> 1][(j & 1) * 2 + 0] = l01;
                pal[j >> 1][(j & 1) * 2 + 1] = l23;
            }
            sum0 += __shfl_xor_sync(0xffffffffu, sum0, 1);
            sum0 += __shfl_xor_sync(0xffffffffu, sum0, 2);
            sum1 += __shfl_xor_sync(0xffffffffu, sum1, 1);
            sum1 += __shfl_xor_sync(0xffffffffu, sum1, 2);
            lrow[0] = lrow[0] * corr0 + sum0;
            lrow[1] = lrow[1] * corr1 + sum1;
            #pragma unroll
            for (int j = 0; j < 8; j++) {
                o[j][0] *= corr0; o[j][1] *= corr0;
                o[j][2] *= corr1; o[j][3] *= corr1;
            }

            // ---- O += P * V^T (3 split terms) ----
            #pragma unroll
            for (int ks = 0; ks < 4; ks++) {
                uint32_t vhf[8][2], vlf[8][2];
                #pragma unroll
                for (int p = 0; p < 4; p++) {
                    uint32_t bd = st + 2 * OPB + (p * 16 + brow) * ROWB + (bkb + ks * 16) * 2;
                    uint32_t t4[4];
                    LDMX4(t4, bd);
                    vhf[p*2][0] = t4[0]; vhf[p*2][1] = t4[1];
                    vhf[p*2+1][0] = t4[2]; vhf[p*2+1][1] = t4[3];
                    LDMX4(t4, bd + OPB);
                    vlf[p*2][0] = t4[0]; vlf[p*2][1] = t4[1];
                    vlf[p*2+1][0] = t4[2]; vlf[p*2+1][1] = t4[3];
                }
                #pragma unroll
                for (int j = 0; j < 8; j++) MMA_BF16(o[j], pah[ks], vhf[j]);
                #pragma unroll
                for (int j = 0; j < 8; j++) MMA_BF16(o[j], pal[ks], vhf[j]);
                #pragma unroll
                for (int j = 0; j < 8; j++) MMA_BF16(o[j], pah[ks], vlf[j]);
            }
        }
        __syncthreads();
    }

    // ---- shaped epilogue: write g_AM hi/lo directly ----
    const float rgv = RG[h], sgv = SG[h], cgv = CG[h];
    const float inv0 = 1.f / lrow[0], inv1 = 1.f / lrow[1];
    const int row0 = q0 + 16 * w + g;
    const size_t vbase = (size_t)bh * 2048 * 64;
    const size_t amr0 = (size_t)((bh >> 4) * 2048 + row0);
    const int colb = h * 64;
    const float s0c = rgv * inv0, s1c = rgv * inv1;
    #pragma unroll
    for (int j = 0; j < 8; j++) {
        int hd = 8 * j + t2;
        float2 v0  = *(const float2*)&g_v [vbase + (size_t)row0 * 64 + hd];
        float2 pm0 = *(const float2*)&g_pm[vbase + (size_t)row0 * 64 + hd];
        float r0 = fmaf(s0c, o[j][0], fmaf(sgv, v0.x, -cgv * pm0.x));
        float r1 = fmaf(s0c, o[j][1], fmaf(sgv, v0.y, -cgv * pm0.y));
        uint32_t hp, lp; split2(r0, r1, hp, lp);
        *(uint32_t*)(g_AM_hi + amr0 * 1024 + colb + hd) = hp;
        *(uint32_t*)(g_AM_lo + amr0 * 1024 + colb + hd) = lp;

        float2 v1  = *(const float2*)&g_v [vbase + (size_t)(row0 + 8) * 64 + hd];
        float2 pm1 = *(const float2*)&g_pm[vbase + (size_t)(row0 + 8) * 64 + hd];
        float r2 = fmaf(s1c, o[j][2], fmaf(sgv, v1.x, -cgv * pm1.x));
        float r3 = fmaf(s1c, o[j][3], fmaf(sgv, v1.y, -cgv * pm1.y));
        split2(r2, r3, hp, lp);
        *(uint32_t*)(g_AM_hi + (amr0 + 8) * 1024 + colb + hd) = hp;
        *(uint32_t*)(g_AM_lo + (amr0 + 8) * 1024 + colb + hd) = lp;
    }
}

// ---------------------------------------------------------------------------
extern "C" void kernel_launch(void* const* d_in, const int* in_sizes, int n_in,
                              void* d_out, int out_size)
{
    (void)in_sizes; (void)n_in; (void)out_size;
    const float* x      = (const float*)d_in[0];
    const float* qk_w   = (const float*)d_in[1];
    const float* qk_b   = (const float*)d_in[2];
    const float* v_w    = (const float*)d_in[3];
    const float* cprojw = (const float*)d_in[4];
    const float* rg     = (const float*)d_in[5];
    const float* sg     = (const float*)d_in[6];
    const float* cg     = (const float*)d_in[7];

    cudaFuncSetAttribute(mma_gemm, cudaFuncAttributeMaxDynamicSharedMemorySize, SMEM_GEMM);
    cudaFuncSetAttribute(attn_mma, cudaFuncAttributeMaxDynamicSharedMemorySize, ATTN_SMEM2);

    convert_A<<<2048, 256>>>(x);
    convert_W<<<dim3(64, 32), 256>>>(qk_w,   2048, 0, 0);
    convert_W<<<dim3(32, 32), 256>>>(v_w,    1024, 0, 2048);
    convert_W<<<dim3(32, 32), 256>>>(cprojw, 1024, 1, 0);
    mma_gemm<<<dim3(24, 32), 256, SMEM_GEMM>>>(0, qk_b, nullptr);
    convert_VT<<<dim3(64, 32), 256>>>();
    prefix_kernel<<<BB * HH, 1024>>>();
    attn_mma<<<dim3(16, 32), 256, ATTN_SMEM2>>>(rg, sg, cg);
    mma_gemm<<<dim3(8, 32), 256, SMEM_GEMM>>>(1, nullptr, (float*)d_out);
}

// round 9
// speedup vs baseline: 2.6403x; 1.0744x over previous
#include <cuda_runtime.h>
#include <cuda_bf16.h>
#include <cstdint>

// Problem constants
#define BB  2
#define SS  2048
#define DD  1024
#define HH  16
#define HDD 64

typedef unsigned long long u64;

// ---------------------------------------------------------------------------
// Scratch (device globals; allocation-free rule)
// ---------------------------------------------------------------------------
__device__ float g_v [BB*HH*SS*HDD];   // fp32 natural [bh][s][hd]
__device__ float g_pm[BB*HH*SS*HDD];   // causal prefix-mean of v

// bf16 hi/lo operands
__device__ __nv_bfloat16 g_Qh[BB*HH*SS*HDD];   // [bh][s][hd]
__device__ __nv_bfloat16 g_Ql[BB*HH*SS*HDD];
__device__ __nv_bfloat16 g_Kh[BB*HH*SS*HDD];   // [bh][s][hd]
__device__ __nv_bfloat16 g_Kl[BB*HH*SS*HDD];
__device__ __nv_bfloat16 g_VTh[BB*HH*HDD*SS];  // [bh][hd][s]
__device__ __nv_bfloat16 g_VTl[BB*HH*HDD*SS];

__device__ __nv_bfloat16 g_XA_hi[4096*1024];   // x row-major
__device__ __nv_bfloat16 g_XA_lo[4096*1024];
__device__ __nv_bfloat16 g_AM_hi[4096*1024];   // attention out (written by attn)
__device__ __nv_bfloat16 g_AM_lo[4096*1024];
__device__ __nv_bfloat16 g_WB_hi[3072*1024];   // [n][k]: 0..2047 qk_w^T, 2048.. v_w^T
__device__ __nv_bfloat16 g_WB_lo[3072*1024];
__device__ __nv_bfloat16 g_WC_hi[1024*1024];   // cproj^T [n][k]
__device__ __nv_bfloat16 g_WC_lo[1024*1024];

// ---------------------------------------------------------------------------
// PTX helpers
// ---------------------------------------------------------------------------
__device__ __forceinline__ uint32_t smem_u32(const void* p) {
    uint32_t a;
    asm("{ .reg .u64 t; cvta.to.shared.u64 t, %1; cvt.u32.u64 %0, t; }"
        : "=r"(a) : "l"(p));
    return a;
}

#define CP16(dst, src) \
    asm volatile("cp.async.cg.shared.global [%0], [%1], 16;" \
                 :: "r"(dst), "l"(src) : "memory")
#define CP_COMMIT() asm volatile("cp.async.commit_group;" ::: "memory")
#define CP_WAIT0()  asm volatile("cp.async.wait_group 0;" ::: "memory")

#define LDMX4(r, addr) \
    asm volatile("ldmatrix.sync.aligned.m8n8.x4.shared.b16 {%0,%1,%2,%3}, [%4];" \
                 : "=r"((r)[0]), "=r"((r)[1]), "=r"((r)[2]), "=r"((r)[3]) : "r"(addr))

#define MMA_BF16(d, a, b0, b1) \
    asm volatile("mma.sync.aligned.m16n8k16.row.col.f32.bf16.bf16.f32 " \
                 "{%0,%1,%2,%3}, {%4,%5,%6,%7}, {%8,%9}, {%0,%1,%2,%3};" \
                 : "+f"((d)[0]), "+f"((d)[1]), "+f"((d)[2]), "+f"((d)[3]) \
                 : "r"((a)[0]), "r"((a)[1]), "r"((a)[2]), "r"((a)[3]), \
                   "r"(b0), "r"(b1))

// Split fp32 pair -> bf16 hi pair + lo pair (packed, v0 in low half)
__device__ __forceinline__ void split2(float v0, float v1, uint32_t& hp, uint32_t& lp) {
    asm("cvt.rn.bf16x2.f32 %0, %1, %2;" : "=r"(hp) : "f"(v1), "f"(v0));
    float h0 = __int_as_float(hp << 16);
    float h1 = __int_as_float(hp & 0xFFFF0000u);
    float l0 = v0 - h0, l1 = v1 - h1;
    asm("cvt.rn.bf16x2.f32 %0, %1, %2;" : "=r"(lp) : "f"(l1), "f"(l0));
}

// Fast exp2 (t <= 0), FMA/ALU pipes only, ~2e-6 rel err.
__device__ __forceinline__ float exp2p(float t) {
    t = fmaxf(t, -126.f);
    float z  = t + 12582912.f;          // round-to-nearest integer trick
    float nf = z - 12582912.f;
    float f  = t - nf;
    float p  = 1.3333558146e-3f;
    p = fmaf(p, f, 9.6181291076e-3f);
    p = fmaf(p, f, 5.5504108665e-2f);
    p = fmaf(p, f, 2.4022650696e-1f);
    p = fmaf(p, f, 6.9314718056e-1f);
    p = fmaf(p, f, 1.0f);
    int ib = __float_as_int(z) << 23;   // == n<<23 (mod 2^32)
    return __int_as_float(__float_as_int(p) + ib);
}

// ---------------------------------------------------------------------------
// convert_A: x fp32 [4096][1024] -> g_XA hi/lo
// ---------------------------------------------------------------------------
__global__ __launch_bounds__(256)
void convert_A(const float* __restrict__ src)
{
    size_t base = ((size_t)blockIdx.x * 256 + threadIdx.x) * 8;
    float4 a = *(const float4*)(src + base);
    float4 b = *(const float4*)(src + base + 4);
    float xs[8] = {a.x, a.y, a.z, a.w, b.x, b.y, b.z, b.w};
    union { __nv_bfloat16 h[8]; uint4 u; } ph, pl;
    #pragma unroll
    for (int i = 0; i < 8; i++) {
        __nv_bfloat16 hb = __float2bfloat16(xs[i]);
        ph.h[i] = hb;
        pl.h[i] = __float2bfloat16(xs[i] - __bfloat162float(hb));
    }
    *(uint4*)(g_XA_hi + base) = ph.u;
    *(uint4*)(g_XA_lo + base) = pl.u;
}

// ---------------------------------------------------------------------------
// convert_W: W [1024][N] fp32 -> [n][k] bf16 hi/lo at row offset (transpose)
// ---------------------------------------------------------------------------
__global__ __launch_bounds__(256)
void convert_W(const float* __restrict__ W, int N, int which, int roff)
{
    __shared__ float t[32][33];
    const int n0 = blockIdx.x * 32, k0 = blockIdx.y * 32;
    const int tx = threadIdx.x & 31, ty = threadIdx.x >> 5;
    #pragma unroll
    for (int i = 0; i < 4; i++)
        t[ty + 8*i][tx] = W[(size_t)(k0 + ty + 8*i) * N + n0 + tx];
    __syncthreads();
    __nv_bfloat16* dh = which ? g_WC_hi : g_WB_hi;
    __nv_bfloat16* dl = which ? g_WC_lo : g_WB_lo;
    #pragma unroll
    for (int i = 0; i < 4; i++) {
        float x = t[tx][ty + 8*i];
        __nv_bfloat16 hb = __float2bfloat16(x);
        size_t off = (size_t)(roff + n0 + ty + 8*i) * 1024 + k0 + tx;
        dh[off] = hb;
        dl[off] = __float2bfloat16(x - __bfloat162float(hb));
    }
}

// ---------------------------------------------------------------------------
// convert_VT: g_v [bh][s][hd] fp32 -> g_VT hi/lo [bh][hd][s] bf16
// ---------------------------------------------------------------------------
__global__ __launch_bounds__(256)
void convert_VT()
{
    __shared__ float tb[32][65];
    const int bh = blockIdx.y, s0 = blockIdx.x * 32;
    const int tid = threadIdx.x;
    {
        int r = tid >> 3, c8 = (tid & 7) * 8;
        const float* vp = g_v + ((size_t)bh * 2048 + s0 + r) * 64 + c8;
        float4 a = *(const float4*)vp, b = *(const float4*)(vp + 4);
        tb[r][c8+0]=a.x; tb[r][c8+1]=a.y; tb[r][c8+2]=a.z; tb[r][c8+3]=a.w;
        tb[r][c8+4]=b.x; tb[r][c8+5]=b.y; tb[r][c8+6]=b.z; tb[r][c8+7]=b.w;
    }
    __syncthreads();
    int hd = tid >> 2, sg = (tid & 3) * 8;
    union { __nv_bfloat16 h[8]; uint4 u; } ph, pl;
    #pragma unroll
    for (int i = 0; i < 8; i++) {
        float x = tb[sg + i][hd];
        __nv_bfloat16 hb = __float2bfloat16(x);
        ph.h[i] = hb;
        pl.h[i] = __float2bfloat16(x - __bfloat162float(hb));
    }
    size_t off = ((size_t)bh * 64 + hd) * 2048 + s0 + sg;
    *(uint4*)(g_VTh + off) = ph.u;
    *(uint4*)(g_VTl + off) = pl.u;
}

// ---------------------------------------------------------------------------
// mma.sync bf16-split GEMM (structure = R7, 2 CTAs/SM requested)
// ---------------------------------------------------------------------------
#define SMEM_STAGE 40960
#define SMEM_GEMM  (2 * SMEM_STAGE)

__global__ __launch_bounds__(256, 2)
void mma_gemm(int mode, const float* __restrict__ QKB, float* __restrict__ OUT)
{
    extern __shared__ char smc[];
    const uint32_t sbase = smem_u32(smc);
    const int tid = threadIdx.x, lane = tid & 31, wid = tid >> 5;
    const int nt = blockIdx.x, mt = blockIdx.y;
    const int m0 = mt * 128, n0 = nt * 128;
    const int warpM = wid & 3, warpN = wid >> 2;

    const __nv_bfloat16 *Ah, *Al, *Bh, *Bl;
    if (mode == 0) { Ah = g_XA_hi; Al = g_XA_lo; Bh = g_WB_hi; Bl = g_WB_lo; }
    else           { Ah = g_AM_hi; Al = g_AM_lo; Bh = g_WC_hi; Bl = g_WC_lo; }

    float c[16][4];
    #pragma unroll
    for (int i = 0; i < 16; i++)
        #pragma unroll
        for (int j = 0; j < 4; j++) c[i][j] = 0.f;

    auto load_stage = [&](int it, int buf) {
        const uint32_t st = sbase + buf * SMEM_STAGE;
        const int k0 = it * 32;
        #pragma unroll
        for (int cc = 0; cc < 8; cc++) {
            int id  = cc * 256 + tid;
            int arr = id >> 9, rem = id & 511, row = rem >> 2, kq = rem & 3;
            const __nv_bfloat16* g = (arr == 0) ? Ah : (arr == 1) ? Al
                                   : (arr == 2) ? Bh : Bl;
            int grow = (arr < 2) ? (m0 + row) : (n0 + row);
            const void* src = g + (size_t)grow * 1024 + k0 + kq * 8;
            uint32_t dst = st + arr * 10240 + row * 80 + kq * 16;
            CP16(dst, src);
        }
        CP_COMMIT();
    };

    load_stage(0, 0);
    for (int it = 0; it < 32; it++) {
        CP_WAIT0();
        __syncthreads();
        if (it + 1 < 32) load_stage(it + 1, (it + 1) & 1);
        const uint32_t st = sbase + (it & 1) * SMEM_STAGE;

        const int matq = lane >> 3, r8 = lane & 7;
        #pragma unroll
        for (int kh = 0; kh < 2; kh++) {
            uint32_t ah[2][4], al[2][4];
            const int arow = ((matq & 1) << 3) + r8;
            const int akof = (((matq >> 1) << 3) + kh * 16) * 2;
            #pragma unroll
            for (int mt2 = 0; mt2 < 2; mt2++) {
                int row = warpM * 32 + mt2 * 16 + arow;
                uint32_t ad = st + row * 80 + akof;
                LDMX4(ah[mt2], ad);
                LDMX4(al[mt2], ad + 10240);
            }
            const int brow = ((matq >> 1) << 3) + r8;
            const int bkof = (((matq & 1) << 3) + kh * 16) * 2;
            #pragma unroll
            for (int p = 0; p < 4; p++) {
                int row = warpN * 64 + p * 16 + brow;
                uint32_t bd = st + 2 * 10240 + row * 80 + bkof;
                uint32_t th[4], tl[4];
                LDMX4(th, bd);
                LDMX4(tl, bd + 10240);
                #pragma unroll
                for (int mt2 = 0; mt2 < 2; mt2++) {
                    MMA_BF16(c[mt2*8 + 2*p],     ah[mt2], th[0], th[1]);
                    MMA_BF16(c[mt2*8 + 2*p + 1], ah[mt2], th[2], th[3]);
                    MMA_BF16(c[mt2*8 + 2*p],     al[mt2], th[0], th[1]);
                    MMA_BF16(c[mt2*8 + 2*p + 1], al[mt2], th[2], th[3]);
                    MMA_BF16(c[mt2*8 + 2*p],     ah[mt2], tl[0], tl[1]);
                    MMA_BF16(c[mt2*8 + 2*p + 1], ah[mt2], tl[2], tl[3]);
                }
            }
        }
        __syncthreads();
    }

    if (mode == 1) {
        #pragma unroll
        for (int mt2 = 0; mt2 < 2; mt2++)
            #pragma unroll
            for (int n2 = 0; n2 < 8; n2++) {
                float* f = c[mt2*8+n2];
                int r0 = m0 + warpM * 32 + mt2 * 16 + (lane >> 2);
                int cb = n0 + warpN * 64 + n2 * 8 + (lane & 3) * 2;
                *(float2*)&OUT[(size_t)r0 * 1024 + cb]       = make_float2(f[0], f[1]);
                *(float2*)&OUT[(size_t)(r0 + 8) * 1024 + cb] = make_float2(f[2], f[3]);
            }
    } else {
        #pragma unroll
        for (int mt2 = 0; mt2 < 2; mt2++)
            #pragma unroll
            for (int n2 = 0; n2 < 8; n2++) {
                float* f = c[mt2*8+n2];
                int r0 = m0 + warpM * 32 + mt2 * 16 + (lane >> 2);
                int cb = n0 + warpN * 64 + n2 * 8 + (lane & 3) * 2;
                #pragma unroll
                for (int rr = 0; rr < 2; rr++) {
                    int mm = r0 + rr * 8;
                    int bb = mm >> 11, ss = mm & 2047;
                    float v0 = f[rr*2], v1 = f[rr*2+1];
                    if (cb < 2048) {
                        v0 += QKB[cb]; v1 += QKB[cb+1];
                        int colg = cb & 1023, hh = colg >> 6, hd = colg & 63;
                        size_t off = ((size_t)(bb * 16 + hh) * 2048 + ss) * 64 + hd;
                        uint32_t hp, lp; split2(v0, v1, hp, lp);
                        if (cb < 1024) { *(uint32_t*)(g_Qh + off) = hp;
                                         *(uint32_t*)(g_Ql + off) = lp; }
                        else           { *(uint32_t*)(g_Kh + off) = hp;
                                         *(uint32_t*)(g_Kl + off) = lp; }
                    } else {
                        int colg = cb - 2048, hh = colg >> 6, hd = colg & 63;
                        *(float2*)&g_v[((size_t)(bb * 16 + hh) * 2048 + ss) * 64 + hd] =
                            make_float2(v0, v1);
                    }
                }
            }
    }
}

// ---------------------------------------------------------------------------
// prefix mean of v: grid (32 bh, 2 hd-halves), block 1024 = 32 chunks x 32 hd
// ---------------------------------------------------------------------------
__global__ __launch_bounds__(1024)
void prefix_kernel()
{
    const int bh = blockIdx.x;
    const int hd = (blockIdx.y << 5) + (threadIdx.x & 31);
    const int c  = threadIdx.x >> 5;            // 0..31, chunk of 64 rows
    const float* vp = g_v  + (size_t)bh * SS * HDD;
    float*       pp = g_pm + (size_t)bh * SS * HDD;
    __shared__ float cs[32][33];

    const int s0 = c * 64;
    float acc = 0.f;
    #pragma unroll 4
    for (int i = 0; i < 64; i++) acc += vp[(s0 + i) * 64 + hd];
    cs[c][threadIdx.x & 31] = acc;
    __syncthreads();

    float off = 0.f;
    for (int cc = 0; cc < c; cc++) off += cs[cc][threadIdx.x & 31];

    float run = off;
    #pragma unroll 4
    for (int i = 0; i < 64; i++) {
        int s = s0 + i;
        run += vp[s * 64 + hd];
        pp[s * 64 + hd] = run / (float)(s + 1);
    }
}

// ---------------------------------------------------------------------------
// Flash attention on mma.sync (bf16 hi/lo split), 2 CTAs/SM requested.
// Block: 128 q x (bh).  8 warps, 16 q-rows per warp.  kv tiles of 64.
// ---------------------------------------------------------------------------
#define ROWB 144
#define OPB  (64 * ROWB)      // 9216
#define STAGEB (4 * OPB)      // 36864
#define ATTN_SMEM2 (2 * STAGEB)

__global__ __launch_bounds__(256, 2)
void attn_mma(const float* __restrict__ RG, const float* __restrict__ SG,
              const float* __restrict__ CG)
{
    extern __shared__ char smc[];
    const uint32_t sb = smem_u32(smc);
    const int tid = threadIdx.x, lane = tid & 31, w = tid >> 5;
    const int qt = (gridDim.x - 1) - blockIdx.x;
    const int bh = blockIdx.y, h = bh & 15;
    const int q0 = qt * 128;

    const __nv_bfloat16* Qh = g_Qh + (size_t)bh * 2048 * 64;
    const __nv_bfloat16* Ql = g_Ql + (size_t)bh * 2048 * 64;
    const __nv_bfloat16* Kh = g_Kh + (size_t)bh * 2048 * 64;
    const __nv_bfloat16* Kl = g_Kl + (size_t)bh * 2048 * 64;
    const __nv_bfloat16* VTh = g_VTh + (size_t)bh * 64 * 2048;
    const __nv_bfloat16* VTl = g_VTl + (size_t)bh * 64 * 2048;

    // ---- stage Q (128 rows x 128B, hi then lo) into stage0 region ----
    #pragma unroll
    for (int cc = 0; cc < 8; cc++) {
        int id = cc * 256 + tid;            // 0..2047
        int half = id >> 10;
        int rem = id & 1023, row = rem >> 3, kq = rem & 7;
        const __nv_bfloat16* src = (half ? Ql : Qh) + (size_t)(q0 + row) * 64 + kq * 8;
        CP16(sb + half * 18432 + row * ROWB + kq * 16, src);
    }
    CP_COMMIT(); CP_WAIT0();
    __syncthreads();

    // ---- extract persistent Q A-frags (4 ksteps, hi/lo) ----
    const int matq = lane >> 3, r8 = lane & 7;
    const int arow = ((matq & 1) << 3) + r8;
    const int akb  = ((matq >> 1) << 3);
    uint32_t qfh[4][4], qfl[4][4];
    #pragma unroll
    for (int ks = 0; ks < 4; ks++) {
        uint32_t ad = sb + (16 * w + arow) * ROWB + (akb + ks * 16) * 2;
        LDMX4(qfh[ks], ad);
        LDMX4(qfl[ks], ad + 18432);
    }
    __syncthreads();   // Q staging free before KV loads overwrite it

    float o[8][4];
    #pragma unroll
    for (int j = 0; j < 8; j++)
        #pragma unroll
        for (int e = 0; e < 4; e++) o[j][e] = 0.f;
    float mrow[2] = { -1e30f, -1e30f }, lrow[2] = { 0.f, 0.f };

    const int ntiles = 2 * qt + 2;
    const int brow = ((matq >> 1) << 3) + r8;
    const int bkb  = ((matq & 1) << 3);
    const int g = lane >> 2, t2 = (lane & 3) * 2;
    const float cexp = 0.125f * 1.44269504f;

    auto load_kv = [&](int t, int buf) {
        const uint32_t st = sb + buf * STAGEB;
        const int k0 = t * 64;
        #pragma unroll
        for (int cc = 0; cc < 8; cc++) {
            int id = cc * 256 + tid;
            int arr = id >> 9, rem = id & 511, row = rem >> 3, kq = rem & 7;
            const __nv_bfloat16* gp;
            size_t goff;
            if (arr < 2) { gp = arr ? Kl : Kh; goff = (size_t)(k0 + row) * 64 + kq * 8; }
            else { gp = (arr == 2) ? VTh : VTl; goff = (size_t)row * 2048 + k0 + kq * 8; }
            CP16(st + arr * OPB + row * ROWB + kq * 16, gp + goff);
        }
        CP_COMMIT();
    };

    load_kv(0, 0);
    for (int t = 0; t < ntiles; t++) {
        CP_WAIT0();
        __syncthreads();
        if (t + 1 < ntiles) load_kv(t + 1, (t + 1) & 1);
        const uint32_t st = sb + (t & 1) * STAGEB;
        const int k0 = t * 64;
        const bool active = (k0 <= q0 + 16 * w + 15);

        if (active) {
            // ---- S = Q K^T (3 split terms), B frags streamed per-p ----
            float s[8][4];
            #pragma unroll
            for (int j = 0; j < 8; j++)
                #pragma unroll
                for (int e = 0; e < 4; e++) s[j][e] = 0.f;

            #pragma unroll
            for (int ks = 0; ks < 4; ks++) {
                #pragma unroll
                for (int p = 0; p < 4; p++) {
                    uint32_t bd = st + (p * 16 + brow) * ROWB + (bkb + ks * 16) * 2;
                    uint32_t th[4], tl[4];
                    LDMX4(th, bd);
                    LDMX4(tl, bd + OPB);
                    MMA_BF16(s[2*p],   qfh[ks], th[0], th[1]);
                    MMA_BF16(s[2*p+1], qfh[ks], th[2], th[3]);
                    MMA_BF16(s[2*p],   qfl[ks], th[0], th[1]);
                    MMA_BF16(s[2*p+1], qfl[ks], th[2], th[3]);
                    MMA_BF16(s[2*p],   qfh[ks], tl[0], tl[1]);
                    MMA_BF16(s[2*p+1], qfh[ks], tl[2], tl[3]);
                }
            }

            // ---- causal mask ----
            const int qrow0 = q0 + 16 * w + g;
            if (k0 + 63 > q0 + 16 * w) {
                #pragma unroll
                for (int j = 0; j < 8; j++) {
                    int kc = k0 + 8 * j + t2;
                    if (kc     > qrow0)     s[j][0] = -1e30f;
                    if (kc + 1 > qrow0)     s[j][1] = -1e30f;
                    if (kc     > qrow0 + 8) s[j][2] = -1e30f;
                    if (kc + 1 > qrow0 + 8) s[j][3] = -1e30f;
                }
            }

            // ---- online softmax ----
            float mx0 = -1e30f, mx1 = -1e30f;
            #pragma unroll
            for (int j = 0; j < 8; j++) {
                mx0 = fmaxf(mx0, fmaxf(s[j][0], s[j][1]));
                mx1 = fmaxf(mx1, fmaxf(s[j][2], s[j][3]));
            }
            mx0 = fmaxf(mx0, __shfl_xor_sync(0xffffffffu, mx0, 1));
            mx0 = fmaxf(mx0, __shfl_xor_sync(0xffffffffu, mx0, 2));
            mx1 = fmaxf(mx1, __shfl_xor_sync(0xffffffffu, mx1, 1));
            mx1 = fmaxf(mx1, __shfl_xor_sync(0xffffffffu, mx1, 2));
            float mn0 = fmaxf(mrow[0], mx0), mn1 = fmaxf(mrow[1], mx1);
            float corr0 = exp2p((mrow[0] - mn0) * cexp);
            float corr1 = exp2p((mrow[1] - mn1) * cexp);
            mrow[0] = mn0; mrow[1] = mn1;
            float nm0 = -mn0 * cexp, nm1 = -mn1 * cexp;

            float sum0 = 0.f, sum1 = 0.f;
            uint32_t pah[4][4], pal[4][4];
            #pragma unroll
            for (int j = 0; j < 8; j++) {
                float p0 = exp2p(fmaf(s[j][0], cexp, nm0));
                float p1 = exp2p(fmaf(s[j][1], cexp, nm0));
                float p2 = exp2p(fmaf(s[j][2], cexp, nm1));
                float p3 = exp2p(fmaf(s[j][3], cexp, nm1));
                sum0 += p0 + p1; sum1 += p2 + p3;
                uint32_t h01, l01, h23, l23;
                split2(p0, p1, h01, l01);
                split2(p2, p3, h23, l23);
                pah[j >> 1][(j & 1) * 2 + 0] = h01;
                pah[j >> 1][(j & 1) * 2 + 1] = h23;
                pal[j >> 1][(j & 1) * 2 + 0] = l01;
                pal[j >> 1][(j & 1) * 2 + 1] = l23;
            }
            sum0 += __shfl_xor_sync(0xffffffffu, sum0, 1);
            sum0 += __shfl_xor_sync(0xffffffffu, sum0, 2);
            sum1 += __shfl_xor_sync(0xffffffffu, sum1, 1);
            sum1 += __shfl_xor_sync(0xffffffffu, sum1, 2);
            lrow[0] = lrow[0] * corr0 + sum0;
            lrow[1] = lrow[1] * corr1 + sum1;
            #pragma unroll
            for (int j = 0; j < 8; j++) {
                o[j][0] *= corr0; o[j][1] *= corr0;
                o[j][2] *= corr1; o[j][3] *= corr1;
            }

            // ---- O += P * V^T (3 split terms), V frags streamed per-p ----
            #pragma unroll
            for (int ks = 0; ks < 4; ks++) {
                #pragma unroll
                for (int p = 0; p < 4; p++) {
                    uint32_t bd = st + 2 * OPB + (p * 16 + brow) * ROWB + (bkb + ks * 16) * 2;
                    uint32_t th[4], tl[4];
                    LDMX4(th, bd);
                    LDMX4(tl, bd + OPB);
                    MMA_BF16(o[2*p],   pah[ks], th[0], th[1]);
                    MMA_BF16(o[2*p+1], pah[ks], th[2], th[3]);
                    MMA_BF16(o[2*p],   pal[ks], th[0], th[1]);
                    MMA_BF16(o[2*p+1], pal[ks], th[2], th[3]);
                    MMA_BF16(o[2*p],   pah[ks], tl[0], tl[1]);
                    MMA_BF16(o[2*p+1], pah[ks], tl[2], tl[3]);
                }
            }
        }
        __syncthreads();
    }

    // ---- shaped epilogue: write g_AM hi/lo directly ----
    const float rgv = RG[h], sgv = SG[h], cgv = CG[h];
    const float inv0 = 1.f / lrow[0], inv1 = 1.f / lrow[1];
    const int row0 = q0 + 16 * w + g;
    const size_t vbase = (size_t)bh * 2048 * 64;
    const size_t amr0 = (size_t)((bh >> 4) * 2048 + row0);
    const int colb = h * 64;
    const float s0c = rgv * inv0, s1c = rgv * inv1;
    #pragma unroll
    for (int j = 0; j < 8; j++) {
        int hd = 8 * j + t2;
        float2 v0  = *(const float2*)&g_v [vbase + (size_t)row0 * 64 + hd];
        float2 pm0 = *(const float2*)&g_pm[vbase + (size_t)row0 * 64 + hd];
        float r0 = fmaf(s0c, o[j][0], fmaf(sgv, v0.x, -cgv * pm0.x));
        float r1 = fmaf(s0c, o[j][1], fmaf(sgv, v0.y, -cgv * pm0.y));
        uint32_t hp, lp; split2(r0, r1, hp, lp);
        *(uint32_t*)(g_AM_hi + amr0 * 1024 + colb + hd) = hp;
        *(uint32_t*)(g_AM_lo + amr0 * 1024 + colb + hd) = lp;

        float2 v1  = *(const float2*)&g_v [vbase + (size_t)(row0 + 8) * 64 + hd];
        float2 pm1 = *(const float2*)&g_pm[vbase + (size_t)(row0 + 8) * 64 + hd];
        float r2 = fmaf(s1c, o[j][2], fmaf(sgv, v1.x, -cgv * pm1.x));
        float r3 = fmaf(s1c, o[j][3], fmaf(sgv, v1.y, -cgv * pm1.y));
        split2(r2, r3, hp, lp);
        *(uint32_t*)(g_AM_hi + (amr0 + 8) * 1024 + colb + hd) = hp;
        *(uint32_t*)(g_AM_lo + (amr0 + 8) * 1024 + colb + hd) = lp;
    }
}

// ---------------------------------------------------------------------------
extern "C" void kernel_launch(void* const* d_in, const int* in_sizes, int n_in,
                              void* d_out, int out_size)
{
    (void)in_sizes; (void)n_in; (void)out_size;
    const float* x      = (const float*)d_in[0];
    const float* qk_w   = (const float*)d_in[1];
    const float* qk_b   = (const float*)d_in[2];
    const float* v_w    = (const float*)d_in[3];
    const float* cprojw = (const float*)d_in[4];
    const float* rg     = (const float*)d_in[5];
    const float* sg     = (const float*)d_in[6];
    const float* cg     = (const float*)d_in[7];

    cudaFuncSetAttribute(mma_gemm, cudaFuncAttributeMaxDynamicSharedMemorySize, SMEM_GEMM);
    cudaFuncSetAttribute(attn_mma, cudaFuncAttributeMaxDynamicSharedMemorySize, ATTN_SMEM2);

    convert_A<<<2048, 256>>>(x);
    convert_W<<<dim3(64, 32), 256>>>(qk_w,   2048, 0, 0);
    convert_W<<<dim3(32, 32), 256>>>(v_w,    1024, 0, 2048);
    convert_W<<<dim3(32, 32), 256>>>(cprojw, 1024, 1, 0);
    mma_gemm<<<dim3(24, 32), 256, SMEM_GEMM>>>(0, qk_b, nullptr);
    convert_VT<<<dim3(64, 32), 256>>>();
    prefix_kernel<<<dim3(32, 2), 1024>>>();
    attn_mma<<<dim3(16, 32), 256, ATTN_SMEM2>>>(rg, sg, cg);
    mma_gemm<<<dim3(8, 32), 256, SMEM_GEMM>>>(1, nullptr, (float*)d_out);
}

// round 10
// speedup vs baseline: 3.6782x; 1.3931x over previous
#include <cuda_runtime.h>
#include <cuda_bf16.h>
#include <cuda_fp16.h>
#include <cstdint>

// Problem constants
#define BB  2
#define SS  2048
#define DD  1024
#define HH  16
#define HDD 64

typedef unsigned long long u64;

// ---------------------------------------------------------------------------
// Scratch (device globals; allocation-free rule)
// ---------------------------------------------------------------------------
__device__ float g_v [BB*HH*SS*HDD];   // fp32 natural [bh][s][hd]
__device__ float g_pm[BB*HH*SS*HDD];   // causal prefix-mean of v

// fp16 operands: A-sides split hi/lo, B-sides single
__device__ __half g_Qh[BB*HH*SS*HDD];   // [bh][s][hd]  (split)
__device__ __half g_Ql[BB*HH*SS*HDD];
__device__ __half g_Kh[BB*HH*SS*HDD];   // [bh][s][hd]  (single)
__device__ __half g_VTh[BB*HH*HDD*SS];  // [bh][hd][s]  (single)

__device__ __half g_XA_hi[4096*1024];   // x row-major (split)
__device__ __half g_XA_lo[4096*1024];
__device__ __half g_AM_hi[4096*1024];   // attention out (split)
__device__ __half g_AM_lo[4096*1024];
__device__ __half g_WB[3072*1024];      // [n][k]: 0..2047 qk_w^T, 2048.. v_w^T (single)
__device__ __half g_WC[1024*1024];      // cproj^T [n][k] (single)

// ---------------------------------------------------------------------------
// PTX helpers
// ---------------------------------------------------------------------------
__device__ __forceinline__ uint32_t smem_u32(const void* p) {
    uint32_t a;
    asm("{ .reg .u64 t; cvta.to.shared.u64 t, %1; cvt.u32.u64 %0, t; }"
        : "=r"(a) : "l"(p));
    return a;
}

#define CP16(dst, src) \
    asm volatile("cp.async.cg.shared.global [%0], [%1], 16;" \
                 :: "r"(dst), "l"(src) : "memory")
#define CP_COMMIT() asm volatile("cp.async.commit_group;" ::: "memory")
#define CP_WAIT0()  asm volatile("cp.async.wait_group 0;" ::: "memory")

#define LDMX4(r, addr) \
    asm volatile("ldmatrix.sync.aligned.m8n8.x4.shared.b16 {%0,%1,%2,%3}, [%4];" \
                 : "=r"((r)[0]), "=r"((r)[1]), "=r"((r)[2]), "=r"((r)[3]) : "r"(addr))

#define MMA_F16(d, a, b0, b1) \
    asm volatile("mma.sync.aligned.m16n8k16.row.col.f32.f16.f16.f32 " \
                 "{%0,%1,%2,%3}, {%4,%5,%6,%7}, {%8,%9}, {%0,%1,%2,%3};" \
                 : "+f"((d)[0]), "+f"((d)[1]), "+f"((d)[2]), "+f"((d)[3]) \
                 : "r"((a)[0]), "r"((a)[1]), "r"((a)[2]), "r"((a)[3]), \
                   "r"(b0), "r"(b1))

// Split fp32 pair -> fp16 hi pair + lo pair (packed half2, v0 in low half)
__device__ __forceinline__ void split2h(float v0, float v1, uint32_t& hp, uint32_t& lp) {
    __half2 h = __floats2half2_rn(v0, v1);
    hp = *reinterpret_cast<uint32_t*>(&h);
    float2 f = __half22float2(h);
    __half2 l = __floats2half2_rn(v0 - f.x, v1 - f.y);
    lp = *reinterpret_cast<uint32_t*>(&l);
}
__device__ __forceinline__ uint32_t pack2h(float v0, float v1) {
    __half2 h = __floats2half2_rn(v0, v1);
    return *reinterpret_cast<uint32_t*>(&h);
}

// Fast exp2 (t <= 0), FMA/ALU pipes only, ~2e-6 rel err.
__device__ __forceinline__ float exp2p(float t) {
    t = fmaxf(t, -126.f);
    float z  = t + 12582912.f;          // round-to-nearest integer trick
    float nf = z - 12582912.f;
    float f  = t - nf;
    float p  = 1.3333558146e-3f;
    p = fmaf(p, f, 9.6181291076e-3f);
    p = fmaf(p, f, 5.5504108665e-2f);
    p = fmaf(p, f, 2.4022650696e-1f);
    p = fmaf(p, f, 6.9314718056e-1f);
    p = fmaf(p, f, 1.0f);
    int ib = __float_as_int(z) << 23;   // == n<<23 (mod 2^32)
    return __int_as_float(__float_as_int(p) + ib);
}

// ---------------------------------------------------------------------------
// convert_A: x fp32 [4096][1024] -> g_XA hi/lo fp16
// ---------------------------------------------------------------------------
__global__ __launch_bounds__(256)
void convert_A(const float* __restrict__ src)
{
    size_t base = ((size_t)blockIdx.x * 256 + threadIdx.x) * 8;
    float4 a = *(const float4*)(src + base);
    float4 b = *(const float4*)(src + base + 4);
    float xs[8] = {a.x, a.y, a.z, a.w, b.x, b.y, b.z, b.w};
    union { __half h[8]; uint4 u; } ph, pl;
    #pragma unroll
    for (int i = 0; i < 8; i++) {
        __half hb = __float2half_rn(xs[i]);
        ph.h[i] = hb;
        pl.h[i] = __float2half_rn(xs[i] - __half2float(hb));
    }
    *(uint4*)(g_XA_hi + base) = ph.u;
    *(uint4*)(g_XA_lo + base) = pl.u;
}

// ---------------------------------------------------------------------------
// convert_W: W [1024][N] fp32 -> [n][k] fp16 single at row offset (transpose)
// ---------------------------------------------------------------------------
__global__ __launch_bounds__(256)
void convert_W(const float* __restrict__ W, int N, int which, int roff)
{
    __shared__ float t[32][33];
    const int n0 = blockIdx.x * 32, k0 = blockIdx.y * 32;
    const int tx = threadIdx.x & 31, ty = threadIdx.x >> 5;
    #pragma unroll
    for (int i = 0; i < 4; i++)
        t[ty + 8*i][tx] = W[(size_t)(k0 + ty + 8*i) * N + n0 + tx];
    __syncthreads();
    __half* dh = which ? g_WC : g_WB;
    #pragma unroll
    for (int i = 0; i < 4; i++) {
        float x = t[tx][ty + 8*i];
        size_t off = (size_t)(roff + n0 + ty + 8*i) * 1024 + k0 + tx;
        dh[off] = __float2half_rn(x);
    }
}

// ---------------------------------------------------------------------------
// convert_VT: g_v [bh][s][hd] fp32 -> g_VTh [bh][hd][s] fp16 single
// ---------------------------------------------------------------------------
__global__ __launch_bounds__(256)
void convert_VT()
{
    __shared__ float tb[32][65];
    const int bh = blockIdx.y, s0 = blockIdx.x * 32;
    const int tid = threadIdx.x;
    {
        int r = tid >> 3, c8 = (tid & 7) * 8;
        const float* vp = g_v + ((size_t)bh * 2048 + s0 + r) * 64 + c8;
        float4 a = *(const float4*)vp, b = *(const float4*)(vp + 4);
        tb[r][c8+0]=a.x; tb[r][c8+1]=a.y; tb[r][c8+2]=a.z; tb[r][c8+3]=a.w;
        tb[r][c8+4]=b.x; tb[r][c8+5]=b.y; tb[r][c8+6]=b.z; tb[r][c8+7]=b.w;
    }
    __syncthreads();
    int hd = tid >> 2, sg = (tid & 3) * 8;
    union { __half h[8]; uint4 u; } ph;
    #pragma unroll
    for (int i = 0; i < 8; i++)
        ph.h[i] = __float2half_rn(tb[sg + i][hd]);
    size_t off = ((size_t)bh * 64 + hd) * 2048 + s0 + sg;
    *(uint4*)(g_VTh + off) = ph.u;
}

// ---------------------------------------------------------------------------
// mma.sync fp16 2-term GEMM.  C = Ah*B + Al*B  (A split, B single fp16).
// Block 128x128, K=1024 in 32-chunks, cp.async double buffer, 2 CTAs/SM.
// stage: Ah|Al|B, each 128 rows x 80B = 10240B -> 30720B/stage.
// ---------------------------------------------------------------------------
#define SMEM_STAGE 30720
#define SMEM_GEMM  (2 * SMEM_STAGE)

__global__ __launch_bounds__(256, 2)
void mma_gemm(int mode, const float* __restrict__ QKB, float* __restrict__ OUT)
{
    extern __shared__ char smc[];
    const uint32_t sbase = smem_u32(smc);
    const int tid = threadIdx.x, lane = tid & 31, wid = tid >> 5;
    const int nt = blockIdx.x, mt = blockIdx.y;
    const int m0 = mt * 128, n0 = nt * 128;
    const int warpM = wid & 3, warpN = wid >> 2;

    const __half *Ah, *Al, *Bs;
    if (mode == 0) { Ah = g_XA_hi; Al = g_XA_lo; Bs = g_WB; }
    else           { Ah = g_AM_hi; Al = g_AM_lo; Bs = g_WC; }

    float c[16][4];
    #pragma unroll
    for (int i = 0; i < 16; i++)
        #pragma unroll
        for (int j = 0; j < 4; j++) c[i][j] = 0.f;

    // 3 arrays x 512 16B-chunks = 1536 chunks, 6 per thread
    auto load_stage = [&](int it, int buf) {
        const uint32_t st = sbase + buf * SMEM_STAGE;
        const int k0 = it * 32;
        #pragma unroll
        for (int cc = 0; cc < 6; cc++) {
            int id  = cc * 256 + tid;
            int arr = id >> 9, rem = id & 511, row = rem >> 2, kq = rem & 3;
            const __half* g = (arr == 0) ? Ah : (arr == 1) ? Al : Bs;
            int grow = (arr < 2) ? (m0 + row) : (n0 + row);
            const void* src = g + (size_t)grow * 1024 + k0 + kq * 8;
            uint32_t dst = st + arr * 10240 + row * 80 + kq * 16;
            CP16(dst, src);
        }
        CP_COMMIT();
    };

    load_stage(0, 0);
    for (int it = 0; it < 32; it++) {
        CP_WAIT0();
        __syncthreads();
        if (it + 1 < 32) load_stage(it + 1, (it + 1) & 1);
        const uint32_t st = sbase + (it & 1) * SMEM_STAGE;

        const int matq = lane >> 3, r8 = lane & 7;
        #pragma unroll
        for (int kh = 0; kh < 2; kh++) {
            uint32_t ah[2][4], al[2][4];
            const int arow = ((matq & 1) << 3) + r8;
            const int akof = (((matq >> 1) << 3) + kh * 16) * 2;
            #pragma unroll
            for (int mt2 = 0; mt2 < 2; mt2++) {
                int row = warpM * 32 + mt2 * 16 + arow;
                uint32_t ad = st + row * 80 + akof;
                LDMX4(ah[mt2], ad);
                LDMX4(al[mt2], ad + 10240);
            }
            const int brow = ((matq >> 1) << 3) + r8;
            const int bkof = (((matq & 1) << 3) + kh * 16) * 2;
            #pragma unroll
            for (int p = 0; p < 4; p++) {
                int row = warpN * 64 + p * 16 + brow;
                uint32_t bd = st + 2 * 10240 + row * 80 + bkof;
                uint32_t th[4];
                LDMX4(th, bd);
                #pragma unroll
                for (int mt2 = 0; mt2 < 2; mt2++) {
                    MMA_F16(c[mt2*8 + 2*p],     ah[mt2], th[0], th[1]);
                    MMA_F16(c[mt2*8 + 2*p + 1], ah[mt2], th[2], th[3]);
                    MMA_F16(c[mt2*8 + 2*p],     al[mt2], th[0], th[1]);
                    MMA_F16(c[mt2*8 + 2*p + 1], al[mt2], th[2], th[3]);
                }
            }
        }
        __syncthreads();
    }

    if (mode == 1) {
        #pragma unroll
        for (int mt2 = 0; mt2 < 2; mt2++)
            #pragma unroll
            for (int n2 = 0; n2 < 8; n2++) {
                float* f = c[mt2*8+n2];
                int r0 = m0 + warpM * 32 + mt2 * 16 + (lane >> 2);
                int cb = n0 + warpN * 64 + n2 * 8 + (lane & 3) * 2;
                *(float2*)&OUT[(size_t)r0 * 1024 + cb]       = make_float2(f[0], f[1]);
                *(float2*)&OUT[(size_t)(r0 + 8) * 1024 + cb] = make_float2(f[2], f[3]);
            }
    } else {
        #pragma unroll
        for (int mt2 = 0; mt2 < 2; mt2++)
            #pragma unroll
            for (int n2 = 0; n2 < 8; n2++) {
                float* f = c[mt2*8+n2];
                int r0 = m0 + warpM * 32 + mt2 * 16 + (lane >> 2);
                int cb = n0 + warpN * 64 + n2 * 8 + (lane & 3) * 2;
                #pragma unroll
                for (int rr = 0; rr < 2; rr++) {
                    int mm = r0 + rr * 8;
                    int bb = mm >> 11, ss = mm & 2047;
                    float v0 = f[rr*2], v1 = f[rr*2+1];
                    if (cb < 2048) {
                        v0 += QKB[cb]; v1 += QKB[cb+1];
                        int colg = cb & 1023, hh = colg >> 6, hd = colg & 63;
                        size_t off = ((size_t)(bb * 16 + hh) * 2048 + ss) * 64 + hd;
                        if (cb < 1024) {
                            uint32_t hp, lp; split2h(v0, v1, hp, lp);
                            *(uint32_t*)(g_Qh + off) = hp;
                            *(uint32_t*)(g_Ql + off) = lp;
                        } else {
                            *(uint32_t*)(g_Kh + off) = pack2h(v0, v1);
                        }
                    } else {
                        int colg = cb - 2048, hh = colg >> 6, hd = colg & 63;
                        *(float2*)&g_v[((size_t)(bb * 16 + hh) * 2048 + ss) * 64 + hd] =
                            make_float2(v0, v1);
                    }
                }
            }
    }
}

// ---------------------------------------------------------------------------
// prefix mean of v: grid (32 bh, 2 hd-halves), block 1024 = 32 chunks x 32 hd
// ---------------------------------------------------------------------------
__global__ __launch_bounds__(1024)
void prefix_kernel()
{
    const int bh = blockIdx.x;
    const int hd = (blockIdx.y << 5) + (threadIdx.x & 31);
    const int c  = threadIdx.x >> 5;            // 0..31, chunk of 64 rows
    const float* vp = g_v  + (size_t)bh * SS * HDD;
    float*       pp = g_pm + (size_t)bh * SS * HDD;
    __shared__ float cs[32][33];

    const int s0 = c * 64;
    float acc = 0.f;
    #pragma unroll 4
    for (int i = 0; i < 64; i++) acc += vp[(s0 + i) * 64 + hd];
    cs[c][threadIdx.x & 31] = acc;
    __syncthreads();

    float off = 0.f;
    for (int cc = 0; cc < c; cc++) off += cs[cc][threadIdx.x & 31];

    float run = off;
    #pragma unroll 4
    for (int i = 0; i < 64; i++) {
        int s = s0 + i;
        run += vp[s * 64 + hd];
        pp[s * 64 + hd] = run / (float)(s + 1);
    }
}

// ---------------------------------------------------------------------------
// Flash attention on mma.sync fp16 (Q and P split, K and V single), 2 CTAs/SM.
// Block: 128 q x (bh).  8 warps, 16 q-rows per warp.  kv tiles of 64.
// stage: K | VT, each 64 rows x 144B = 9216B -> 18432B/stage, 2 stages.
// ---------------------------------------------------------------------------
#define ROWB 144
#define OPB  (64 * ROWB)      // 9216
#define STAGEB (2 * OPB)      // 18432
#define ATTN_SMEM2 (2 * STAGEB)

__global__ __launch_bounds__(256, 2)
void attn_mma(const float* __restrict__ RG, const float* __restrict__ SG,
              const float* __restrict__ CG)
{
    extern __shared__ char smc[];
    const uint32_t sb = smem_u32(smc);
    const int tid = threadIdx.x, lane = tid & 31, w = tid >> 5;
    const int qt = (gridDim.x - 1) - blockIdx.x;
    const int bh = blockIdx.y, h = bh & 15;
    const int q0 = qt * 128;

    const __half* Qh = g_Qh + (size_t)bh * 2048 * 64;
    const __half* Ql = g_Ql + (size_t)bh * 2048 * 64;
    const __half* Kh = g_Kh + (size_t)bh * 2048 * 64;
    const __half* VTh = g_VTh + (size_t)bh * 64 * 2048;

    // ---- stage Q (hi at sb, lo at sb+18432; 128 rows x 128B each) ----
    #pragma unroll
    for (int cc = 0; cc < 8; cc++) {
        int id = cc * 256 + tid;            // 0..2047
        int half_ = id >> 10;
        int rem = id & 1023, row = rem >> 3, kq = rem & 7;
        const __half* src = (half_ ? Ql : Qh) + (size_t)(q0 + row) * 64 + kq * 8;
        CP16(sb + half_ * 18432 + row * ROWB + kq * 16, src);
    }
    CP_COMMIT(); CP_WAIT0();
    __syncthreads();

    // ---- extract persistent Q A-frags (4 ksteps, hi/lo) ----
    const int matq = lane >> 3, r8 = lane & 7;
    const int arow = ((matq & 1) << 3) + r8;
    const int akb  = ((matq >> 1) << 3);
    uint32_t qfh[4][4], qfl[4][4];
    #pragma unroll
    for (int ks = 0; ks < 4; ks++) {
        uint32_t ad = sb + (16 * w + arow) * ROWB + (akb + ks * 16) * 2;
        LDMX4(qfh[ks], ad);
        LDMX4(qfl[ks], ad + 18432);
    }
    __syncthreads();   // Q staging free before KV loads overwrite it

    float o[8][4];
    #pragma unroll
    for (int j = 0; j < 8; j++)
        #pragma unroll
        for (int e = 0; e < 4; e++) o[j][e] = 0.f;
    float mrow[2] = { -1e30f, -1e30f }, lrow[2] = { 0.f, 0.f };

    const int ntiles = 2 * qt + 2;
    const int brow = ((matq >> 1) << 3) + r8;
    const int bkb  = ((matq & 1) << 3);
    const int g = lane >> 2, t2 = (lane & 3) * 2;
    const float cexp = 0.125f * 1.44269504f;

    // K | VT: 2 arrays x 512 chunks = 1024 chunks, 4 per thread
    auto load_kv = [&](int t, int buf) {
        const uint32_t st = sb + buf * STAGEB;
        const int k0 = t * 64;
        #pragma unroll
        for (int cc = 0; cc < 4; cc++) {
            int id = cc * 256 + tid;
            int arr = id >> 9, rem = id & 511, row = rem >> 3, kq = rem & 7;
            const __half* gp = arr ? (VTh + (size_t)row * 2048 + k0 + kq * 8)
                                   : (Kh + (size_t)(k0 + row) * 64 + kq * 8);
            CP16(st + arr * OPB + row * ROWB + kq * 16, gp);
        }
        CP_COMMIT();
    };

    load_kv(0, 0);
    for (int t = 0; t < ntiles; t++) {
        CP_WAIT0();
        __syncthreads();
        if (t + 1 < ntiles) load_kv(t + 1, (t + 1) & 1);
        const uint32_t st = sb + (t & 1) * STAGEB;
        const int k0 = t * 64;
        const bool active = (k0 <= q0 + 16 * w + 15);

        if (active) {
            // ---- S = Q K^T (2 terms: Qh*K + Ql*K) ----
            float s[8][4];
            #pragma unroll
            for (int j = 0; j < 8; j++)
                #pragma unroll
                for (int e = 0; e < 4; e++) s[j][e] = 0.f;

            #pragma unroll
            for (int ks = 0; ks < 4; ks++) {
                #pragma unroll
                for (int p = 0; p < 4; p++) {
                    uint32_t bd = st + (p * 16 + brow) * ROWB + (bkb + ks * 16) * 2;
                    uint32_t th[4];
                    LDMX4(th, bd);
                    MMA_F16(s[2*p],   qfh[ks], th[0], th[1]);
                    MMA_F16(s[2*p+1], qfh[ks], th[2], th[3]);
                    MMA_F16(s[2*p],   qfl[ks], th[0], th[1]);
                    MMA_F16(s[2*p+1], qfl[ks], th[2], th[3]);
                }
            }

            // ---- causal mask ----
            const int qrow0 = q0 + 16 * w + g;
            if (k0 + 63 > q0 + 16 * w) {
                #pragma unroll
                for (int j = 0; j < 8; j++) {
                    int kc = k0 + 8 * j + t2;
                    if (kc     > qrow0)     s[j][0] = -1e30f;
                    if (kc + 1 > qrow0)     s[j][1] = -1e30f;
                    if (kc     > qrow0 + 8) s[j][2] = -1e30f;
                    if (kc + 1 > qrow0 + 8) s[j][3] = -1e30f;
                }
            }

            // ---- online softmax ----
            float mx0 = -1e30f, mx1 = -1e30f;
            #pragma unroll
            for (int j = 0; j < 8; j++) {
                mx0 = fmaxf(mx0, fmaxf(s[j][0], s[j][1]));
                mx1 = fmaxf(mx1, fmaxf(s[j][2], s[j][3]));
            }
            mx0 = fmaxf(mx0, __shfl_xor_sync(0xffffffffu, mx0, 1));
            mx0 = fmaxf(mx0, __shfl_xor_sync(0xffffffffu, mx0, 2));
            mx1 = fmaxf(mx1, __shfl_xor_sync(0xffffffffu, mx1, 1));
            mx1 = fmaxf(mx1, __shfl_xor_sync(0xffffffffu, mx1, 2));
            float mn0 = fmaxf(mrow[0], mx0), mn1 = fmaxf(mrow[1], mx1);
            float corr0 = exp2p((mrow[0] - mn0) * cexp);
            float corr1 = exp2p((mrow[1] - mn1) * cexp);
            mrow[0] = mn0; mrow[1] = mn1;
            float nm0 = -mn0 * cexp, nm1 = -mn1 * cexp;

            float sum0 = 0.f, sum1 = 0.f;
            uint32_t pah[4][4], pal[4][4];
            #pragma unroll
            for (int j = 0; j < 8; j++) {
                float p0 = exp2p(fmaf(s[j][0], cexp, nm0));
                float p1 = exp2p(fmaf(s[j][1], cexp, nm0));
                float p2 = exp2p(fmaf(s[j][2], cexp, nm1));
                float p3 = exp2p(fmaf(s[j][3], cexp, nm1));
                sum0 += p0 + p1; sum1 += p2 + p3;
                uint32_t h01, l01, h23, l23;
                split2h(p0, p1, h01, l01);
                split2h(p2, p3, h23, l23);
                pah[j >> 1][(j & 1) * 2 + 0] = h01;
                pah[j >> 1][(j & 1) * 2 + 1] = h23;
                pal[j >> 1][(j & 1) * 2 + 0] = l01;
                pal[j >> 1][(j & 1) * 2 + 1] = l23;
            }
            sum0 += __shfl_xor_sync(0xffffffffu, sum0, 1);
            sum0 += __shfl_xor_sync(0xffffffffu, sum0, 2);
            sum1 += __shfl_xor_sync(0xffffffffu, sum1, 1);
            sum1 += __shfl_xor_sync(0xffffffffu, sum1, 2);
            lrow[0] = lrow[0] * corr0 + sum0;
            lrow[1] = lrow[1] * corr1 + sum1;
            #pragma unroll
            for (int j = 0; j < 8; j++) {
                o[j][0] *= corr0; o[j][1] *= corr0;
                o[j][2] *= corr1; o[j][3] *= corr1;
            }

            // ---- O += P * V^T (2 terms: Ph*V + Pl*V) ----
            #pragma unroll
            for (int ks = 0; ks < 4; ks++) {
                #pragma unroll
                for (int p = 0; p < 4; p++) {
                    uint32_t bd = st + OPB + (p * 16 + brow) * ROWB + (bkb + ks * 16) * 2;
                    uint32_t th[4];
                    LDMX4(th, bd);
                    MMA_F16(o[2*p],   pah[ks], th[0], th[1]);
                    MMA_F16(o[2*p+1], pah[ks], th[2], th[3]);
                    MMA_F16(o[2*p],   pal[ks], th[0], th[1]);
                    MMA_F16(o[2*p+1], pal[ks], th[2], th[3]);
                }
            }
        }
        __syncthreads();
    }

    // ---- shaped epilogue: write g_AM hi/lo (fp16) ----
    const float rgv = RG[h], sgv = SG[h], cgv = CG[h];
    const float inv0 = 1.f / lrow[0], inv1 = 1.f / lrow[1];
    const int row0 = q0 + 16 * w + g;
    const size_t vbase = (size_t)bh * 2048 * 64;
    const size_t amr0 = (size_t)((bh >> 4) * 2048 + row0);
    const int colb = h * 64;
    const float s0c = rgv * inv0, s1c = rgv * inv1;
    #pragma unroll
    for (int j = 0; j < 8; j++) {
        int hd = 8 * j + t2;
        float2 v0  = *(const float2*)&g_v [vbase + (size_t)row0 * 64 + hd];
        float2 pm0 = *(const float2*)&g_pm[vbase + (size_t)row0 * 64 + hd];
        float r0 = fmaf(s0c, o[j][0], fmaf(sgv, v0.x, -cgv * pm0.x));
        float r1 = fmaf(s0c, o[j][1], fmaf(sgv, v0.y, -cgv * pm0.y));
        uint32_t hp, lp; split2h(r0, r1, hp, lp);
        *(uint32_t*)(g_AM_hi + amr0 * 1024 + colb + hd) = hp;
        *(uint32_t*)(g_AM_lo + amr0 * 1024 + colb + hd) = lp;

        float2 v1  = *(const float2*)&g_v [vbase + (size_t)(row0 + 8) * 64 + hd];
        float2 pm1 = *(const float2*)&g_pm[vbase + (size_t)(row0 + 8) * 64 + hd];
        float r2 = fmaf(s1c, o[j][2], fmaf(sgv, v1.x, -cgv * pm1.x));
        float r3 = fmaf(s1c, o[j][3], fmaf(sgv, v1.y, -cgv * pm1.y));
        split2h(r2, r3, hp, lp);
        *(uint32_t*)(g_AM_hi + (amr0 + 8) * 1024 + colb + hd) = hp;
        *(uint32_t*)(g_AM_lo + (amr0 + 8) * 1024 + colb + hd) = lp;
    }
}

// ---------------------------------------------------------------------------
extern "C" void kernel_launch(void* const* d_in, const int* in_sizes, int n_in,
                              void* d_out, int out_size)
{
    (void)in_sizes; (void)n_in; (void)out_size;
    const float* x      = (const float*)d_in[0];
    const float* qk_w   = (const float*)d_in[1];
    const float* qk_b   = (const float*)d_in[2];
    const float* v_w    = (const float*)d_in[3];
    const float* cprojw = (const float*)d_in[4];
    const float* rg     = (const float*)d_in[5];
    const float* sg     = (const float*)d_in[6];
    const float* cg     = (const float*)d_in[7];

    cudaFuncSetAttribute(mma_gemm, cudaFuncAttributeMaxDynamicSharedMemorySize, SMEM_GEMM);
    cudaFuncSetAttribute(attn_mma, cudaFuncAttributeMaxDynamicSharedMemorySize, ATTN_SMEM2);

    convert_A<<<2048, 256>>>(x);
    convert_W<<<dim3(64, 32), 256>>>(qk_w,   2048, 0, 0);
    convert_W<<<dim3(32, 32), 256>>>(v_w,    1024, 0, 2048);
    convert_W<<<dim3(32, 32), 256>>>(cprojw, 1024, 1, 0);
    mma_gemm<<<dim3(24, 32), 256, SMEM_GEMM>>>(0, qk_b, nullptr);
    convert_VT<<<dim3(64, 32), 256>>>();
    prefix_kernel<<<dim3(32, 2), 1024>>>();
    attn_mma<<<dim3(16, 32), 256, ATTN_SMEM2>>>(rg, sg, cg);
    mma_gemm<<<dim3(8, 32), 256, SMEM_GEMM>>>(1, nullptr, (float*)d_out);
}

// round 11
// speedup vs baseline: 5.5212x; 1.5011x over previous
#include <cuda_runtime.h>
#include <cuda_bf16.h>
#include <cuda_fp16.h>
#include <cstdint>

// Problem constants
#define BB  2
#define SS  2048
#define DD  1024
#define HH  16
#define HDD 64

typedef unsigned long long u64;

// ---------------------------------------------------------------------------
// Scratch (device globals; allocation-free rule)
// ---------------------------------------------------------------------------
__device__ float g_v [BB*HH*SS*HDD];   // fp32 natural [bh][s][hd]
__device__ float g_pm[BB*HH*SS*HDD];   // causal prefix-mean of v

// fp16 operands (single precision level, fp32 accumulate in MMA)
__device__ __half g_Q [BB*HH*SS*HDD];   // [bh][s][hd]
__device__ __half g_K [BB*HH*SS*HDD];   // [bh][s][hd]
__device__ __half g_VT[BB*HH*HDD*SS];   // [bh][hd][s]

__device__ __half g_XA[4096*1024];      // x row-major fp16
__device__ __half g_AM[4096*1024];      // attention out row-major fp16
__device__ __half g_WB[3072*1024];      // [n][k]: 0..2047 qk_w^T, 2048.. v_w^T
__device__ __half g_WC[1024*1024];      // cproj^T [n][k]

// ---------------------------------------------------------------------------
// PTX helpers
// ---------------------------------------------------------------------------
__device__ __forceinline__ uint32_t smem_u32(const void* p) {
    uint32_t a;
    asm("{ .reg .u64 t; cvta.to.shared.u64 t, %1; cvt.u32.u64 %0, t; }"
        : "=r"(a) : "l"(p));
    return a;
}

#define CP16(dst, src) \
    asm volatile("cp.async.cg.shared.global [%0], [%1], 16;" \
                 :: "r"(dst), "l"(src) : "memory")
#define CP_COMMIT() asm volatile("cp.async.commit_group;" ::: "memory")
#define CP_WAIT0()  asm volatile("cp.async.wait_group 0;" ::: "memory")

#define LDMX4(r, addr) \
    asm volatile("ldmatrix.sync.aligned.m8n8.x4.shared.b16 {%0,%1,%2,%3}, [%4];" \
                 : "=r"((r)[0]), "=r"((r)[1]), "=r"((r)[2]), "=r"((r)[3]) : "r"(addr))

#define MMA_F16(d, a, b0, b1) \
    asm volatile("mma.sync.aligned.m16n8k16.row.col.f32.f16.f16.f32 " \
                 "{%0,%1,%2,%3}, {%4,%5,%6,%7}, {%8,%9}, {%0,%1,%2,%3};" \
                 : "+f"((d)[0]), "+f"((d)[1]), "+f"((d)[2]), "+f"((d)[3]) \
                 : "r"((a)[0]), "r"((a)[1]), "r"((a)[2]), "r"((a)[3]), \
                   "r"(b0), "r"(b1))

__device__ __forceinline__ uint32_t pack2h(float v0, float v1) {
    __half2 h = __floats2half2_rn(v0, v1);
    return *reinterpret_cast<uint32_t*>(&h);
}

// Fast exp2 (t <= 0), FMA/ALU pipes only, ~2e-6 rel err.
__device__ __forceinline__ float exp2p(float t) {
    t = fmaxf(t, -126.f);
    float z  = t + 12582912.f;          // round-to-nearest integer trick
    float nf = z - 12582912.f;
    float f  = t - nf;
    float p  = 1.3333558146e-3f;
    p = fmaf(p, f, 9.6181291076e-3f);
    p = fmaf(p, f, 5.5504108665e-2f);
    p = fmaf(p, f, 2.4022650696e-1f);
    p = fmaf(p, f, 6.9314718056e-1f);
    p = fmaf(p, f, 1.0f);
    int ib = __float_as_int(z) << 23;   // == n<<23 (mod 2^32)
    return __int_as_float(__float_as_int(p) + ib);
}

// ---------------------------------------------------------------------------
// convert_A: x fp32 [4096][1024] -> g_XA fp16
// ---------------------------------------------------------------------------
__global__ __launch_bounds__(256)
void convert_A(const float* __restrict__ src)
{
    size_t base = ((size_t)blockIdx.x * 256 + threadIdx.x) * 8;
    float4 a = *(const float4*)(src + base);
    float4 b = *(const float4*)(src + base + 4);
    float xs[8] = {a.x, a.y, a.z, a.w, b.x, b.y, b.z, b.w};
    union { __half h[8]; uint4 u; } ph;
    #pragma unroll
    for (int i = 0; i < 8; i++) ph.h[i] = __float2half_rn(xs[i]);
    *(uint4*)(g_XA + base) = ph.u;
}

// ---------------------------------------------------------------------------
// convert_W: W [1024][N] fp32 -> [n][k] fp16 at row offset (transpose)
// ---------------------------------------------------------------------------
__global__ __launch_bounds__(256)
void convert_W(const float* __restrict__ W, int N, int which, int roff)
{
    __shared__ float t[32][33];
    const int n0 = blockIdx.x * 32, k0 = blockIdx.y * 32;
    const int tx = threadIdx.x & 31, ty = threadIdx.x >> 5;
    #pragma unroll
    for (int i = 0; i < 4; i++)
        t[ty + 8*i][tx] = W[(size_t)(k0 + ty + 8*i) * N + n0 + tx];
    __syncthreads();
    __half* dh = which ? g_WC : g_WB;
    #pragma unroll
    for (int i = 0; i < 4; i++) {
        size_t off = (size_t)(roff + n0 + ty + 8*i) * 1024 + k0 + tx;
        dh[off] = __float2half_rn(t[tx][ty + 8*i]);
    }
}

// ---------------------------------------------------------------------------
// convert_VT: g_v [bh][s][hd] fp32 -> g_VT [bh][hd][s] fp16
// ---------------------------------------------------------------------------
__global__ __launch_bounds__(256)
void convert_VT()
{
    __shared__ float tb[32][65];
    const int bh = blockIdx.y, s0 = blockIdx.x * 32;
    const int tid = threadIdx.x;
    {
        int r = tid >> 3, c8 = (tid & 7) * 8;
        const float* vp = g_v + ((size_t)bh * 2048 + s0 + r) * 64 + c8;
        float4 a = *(const float4*)vp, b = *(const float4*)(vp + 4);
        tb[r][c8+0]=a.x; tb[r][c8+1]=a.y; tb[r][c8+2]=a.z; tb[r][c8+3]=a.w;
        tb[r][c8+4]=b.x; tb[r][c8+5]=b.y; tb[r][c8+6]=b.z; tb[r][c8+7]=b.w;
    }
    __syncthreads();
    int hd = tid >> 2, sg = (tid & 3) * 8;
    union { __half h[8]; uint4 u; } ph;
    #pragma unroll
    for (int i = 0; i < 8; i++)
        ph.h[i] = __float2half_rn(tb[sg + i][hd]);
    size_t off = ((size_t)bh * 64 + hd) * 2048 + s0 + sg;
    *(uint4*)(g_VT + off) = ph.u;
}

// ---------------------------------------------------------------------------
// mma.sync fp16 GEMM.  C = A*B, fp32 accumulate.
// Block 128x128, K=1024 in 32-chunks, cp.async double buffer, 2 CTAs/SM.
// stage: A|B, each 128 rows x 80B = 10240B -> 20480B/stage.
// ---------------------------------------------------------------------------
#define SMEM_STAGE 20480
#define SMEM_GEMM  (2 * SMEM_STAGE)

__global__ __launch_bounds__(256, 2)
void mma_gemm(int mode, const float* __restrict__ QKB, float* __restrict__ OUT)
{
    extern __shared__ char smc[];
    const uint32_t sbase = smem_u32(smc);
    const int tid = threadIdx.x, lane = tid & 31, wid = tid >> 5;
    const int nt = blockIdx.x, mt = blockIdx.y;
    const int m0 = mt * 128, n0 = nt * 128;
    const int warpM = wid & 3, warpN = wid >> 2;

    const __half *As, *Bs;
    if (mode == 0) { As = g_XA; Bs = g_WB; }
    else           { As = g_AM; Bs = g_WC; }

    float c[16][4];
    #pragma unroll
    for (int i = 0; i < 16; i++)
        #pragma unroll
        for (int j = 0; j < 4; j++) c[i][j] = 0.f;

    // 2 arrays x 512 16B-chunks = 1024 chunks, 4 per thread
    auto load_stage = [&](int it, int buf) {
        const uint32_t st = sbase + buf * SMEM_STAGE;
        const int k0 = it * 32;
        #pragma unroll
        for (int cc = 0; cc < 4; cc++) {
            int id  = cc * 256 + tid;
            int arr = id >> 9, rem = id & 511, row = rem >> 2, kq = rem & 3;
            const __half* g = arr ? Bs : As;
            int grow = arr ? (n0 + row) : (m0 + row);
            const void* src = g + (size_t)grow * 1024 + k0 + kq * 8;
            uint32_t dst = st + arr * 10240 + row * 80 + kq * 16;
            CP16(dst, src);
        }
        CP_COMMIT();
    };

    load_stage(0, 0);
    for (int it = 0; it < 32; it++) {
        CP_WAIT0();
        __syncthreads();
        if (it + 1 < 32) load_stage(it + 1, (it + 1) & 1);
        const uint32_t st = sbase + (it & 1) * SMEM_STAGE;

        const int matq = lane >> 3, r8 = lane & 7;
        #pragma unroll
        for (int kh = 0; kh < 2; kh++) {
            uint32_t ah[2][4];
            const int arow = ((matq & 1) << 3) + r8;
            const int akof = (((matq >> 1) << 3) + kh * 16) * 2;
            #pragma unroll
            for (int mt2 = 0; mt2 < 2; mt2++) {
                int row = warpM * 32 + mt2 * 16 + arow;
                LDMX4(ah[mt2], st + row * 80 + akof);
            }
            const int brow = ((matq >> 1) << 3) + r8;
            const int bkof = (((matq & 1) << 3) + kh * 16) * 2;
            #pragma unroll
            for (int p = 0; p < 4; p++) {
                int row = warpN * 64 + p * 16 + brow;
                uint32_t bd = st + 10240 + row * 80 + bkof;
                uint32_t th[4];
                LDMX4(th, bd);
                #pragma unroll
                for (int mt2 = 0; mt2 < 2; mt2++) {
                    MMA_F16(c[mt2*8 + 2*p],     ah[mt2], th[0], th[1]);
                    MMA_F16(c[mt2*8 + 2*p + 1], ah[mt2], th[2], th[3]);
                }
            }
        }
        __syncthreads();
    }

    if (mode == 1) {
        #pragma unroll
        for (int mt2 = 0; mt2 < 2; mt2++)
            #pragma unroll
            for (int n2 = 0; n2 < 8; n2++) {
                float* f = c[mt2*8+n2];
                int r0 = m0 + warpM * 32 + mt2 * 16 + (lane >> 2);
                int cb = n0 + warpN * 64 + n2 * 8 + (lane & 3) * 2;
                *(float2*)&OUT[(size_t)r0 * 1024 + cb]       = make_float2(f[0], f[1]);
                *(float2*)&OUT[(size_t)(r0 + 8) * 1024 + cb] = make_float2(f[2], f[3]);
            }
    } else {
        #pragma unroll
        for (int mt2 = 0; mt2 < 2; mt2++)
            #pragma unroll
            for (int n2 = 0; n2 < 8; n2++) {
                float* f = c[mt2*8+n2];
                int r0 = m0 + warpM * 32 + mt2 * 16 + (lane >> 2);
                int cb = n0 + warpN * 64 + n2 * 8 + (lane & 3) * 2;
                #pragma unroll
                for (int rr = 0; rr < 2; rr++) {
                    int mm = r0 + rr * 8;
                    int bb = mm >> 11, ss = mm & 2047;
                    float v0 = f[rr*2], v1 = f[rr*2+1];
                    if (cb < 2048) {
                        v0 += QKB[cb]; v1 += QKB[cb+1];
                        int colg = cb & 1023, hh = colg >> 6, hd = colg & 63;
                        size_t off = ((size_t)(bb * 16 + hh) * 2048 + ss) * 64 + hd;
                        __half* dst = (cb < 1024) ? g_Q : g_K;
                        *(uint32_t*)(dst + off) = pack2h(v0, v1);
                    } else {
                        int colg = cb - 2048, hh = colg >> 6, hd = colg & 63;
                        *(float2*)&g_v[((size_t)(bb * 16 + hh) * 2048 + ss) * 64 + hd] =
                            make_float2(v0, v1);
                    }
                }
            }
    }
}

// ---------------------------------------------------------------------------
// prefix mean of v: grid (32 bh, 2 hd-halves), block 1024 = 32 chunks x 32 hd
// ---------------------------------------------------------------------------
__global__ __launch_bounds__(1024)
void prefix_kernel()
{
    const int bh = blockIdx.x;
    const int hd = (blockIdx.y << 5) + (threadIdx.x & 31);
    const int c  = threadIdx.x >> 5;            // 0..31, chunk of 64 rows
    const float* vp = g_v  + (size_t)bh * SS * HDD;
    float*       pp = g_pm + (size_t)bh * SS * HDD;
    __shared__ float cs[32][33];

    const int s0 = c * 64;
    float acc = 0.f;
    #pragma unroll 4
    for (int i = 0; i < 64; i++) acc += vp[(s0 + i) * 64 + hd];
    cs[c][threadIdx.x & 31] = acc;
    __syncthreads();

    float off = 0.f;
    for (int cc = 0; cc < c; cc++) off += cs[cc][threadIdx.x & 31];

    float run = off;
    #pragma unroll 4
    for (int i = 0; i < 64; i++) {
        int s = s0 + i;
        run += vp[s * 64 + hd];
        pp[s * 64 + hd] = run / (float)(s + 1);
    }
}

// ---------------------------------------------------------------------------
// Flash attention on mma.sync fp16 (single precision level), 2 CTAs/SM.
// Block: 128 q x (bh).  8 warps, 16 q-rows per warp.  kv tiles of 64.
// stage: K | VT, each 64 rows x 144B = 9216B -> 18432B/stage, 2 stages.
// ---------------------------------------------------------------------------
#define ROWB 144
#define OPB  (64 * ROWB)      // 9216
#define STAGEB (2 * OPB)      // 18432
#define ATTN_SMEM2 (2 * STAGEB)

__global__ __launch_bounds__(256, 2)
void attn_mma(const float* __restrict__ RG, const float* __restrict__ SG,
              const float* __restrict__ CG)
{
    extern __shared__ char smc[];
    const uint32_t sb = smem_u32(smc);
    const int tid = threadIdx.x, lane = tid & 31, w = tid >> 5;
    const int qt = (gridDim.x - 1) - blockIdx.x;
    const int bh = blockIdx.y, h = bh & 15;
    const int q0 = qt * 128;

    const __half* Qp = g_Q + (size_t)bh * 2048 * 64;
    const __half* Kp = g_K + (size_t)bh * 2048 * 64;
    const __half* VTp = g_VT + (size_t)bh * 64 * 2048;

    // ---- stage Q (128 rows x 128B, stride ROWB) into stage0 region ----
    #pragma unroll
    for (int cc = 0; cc < 4; cc++) {
        int id = cc * 256 + tid;            // 0..1023
        int row = id >> 3, kq = id & 7;
        const __half* src = Qp + (size_t)(q0 + row) * 64 + kq * 8;
        CP16(sb + row * ROWB + kq * 16, src);
    }
    CP_COMMIT(); CP_WAIT0();
    __syncthreads();

    // ---- extract persistent Q A-frags (4 ksteps) ----
    const int matq = lane >> 3, r8 = lane & 7;
    const int arow = ((matq & 1) << 3) + r8;
    const int akb  = ((matq >> 1) << 3);
    uint32_t qf[4][4];
    #pragma unroll
    for (int ks = 0; ks < 4; ks++)
        LDMX4(qf[ks], sb + (16 * w + arow) * ROWB + (akb + ks * 16) * 2);
    __syncthreads();   // Q staging free before KV loads overwrite it

    float o[8][4];
    #pragma unroll
    for (int j = 0; j < 8; j++)
        #pragma unroll
        for (int e = 0; e < 4; e++) o[j][e] = 0.f;
    float mrow[2] = { -1e30f, -1e30f }, lrow[2] = { 0.f, 0.f };

    const int ntiles = 2 * qt + 2;
    const int brow = ((matq >> 1) << 3) + r8;
    const int bkb  = ((matq & 1) << 3);
    const int g = lane >> 2, t2 = (lane & 3) * 2;
    const float cexp = 0.125f * 1.44269504f;

    // K | VT: 2 arrays x 512 chunks = 1024 chunks, 4 per thread
    auto load_kv = [&](int t, int buf) {
        const uint32_t st = sb + buf * STAGEB;
        const int k0 = t * 64;
        #pragma unroll
        for (int cc = 0; cc < 4; cc++) {
            int id = cc * 256 + tid;
            int arr = id >> 9, rem = id & 511, row = rem >> 3, kq = rem & 7;
            const __half* gp = arr ? (VTp + (size_t)row * 2048 + k0 + kq * 8)
                                   : (Kp + (size_t)(k0 + row) * 64 + kq * 8);
            CP16(st + arr * OPB + row * ROWB + kq * 16, gp);
        }
        CP_COMMIT();
    };

    load_kv(0, 0);
    for (int t = 0; t < ntiles; t++) {
        CP_WAIT0();
        __syncthreads();
        if (t + 1 < ntiles) load_kv(t + 1, (t + 1) & 1);
        const uint32_t st = sb + (t & 1) * STAGEB;
        const int k0 = t * 64;
        const bool active = (k0 <= q0 + 16 * w + 15);

        if (active) {
            // ---- S = Q K^T ----
            float s[8][4];
            #pragma unroll
            for (int j = 0; j < 8; j++)
                #pragma unroll
                for (int e = 0; e < 4; e++) s[j][e] = 0.f;

            #pragma unroll
            for (int ks = 0; ks < 4; ks++) {
                #pragma unroll
                for (int p = 0; p < 4; p++) {
                    uint32_t bd = st + (p * 16 + brow) * ROWB + (bkb + ks * 16) * 2;
                    uint32_t th[4];
                    LDMX4(th, bd);
                    MMA_F16(s[2*p],   qf[ks], th[0], th[1]);
                    MMA_F16(s[2*p+1], qf[ks], th[2], th[3]);
                }
            }

            // ---- causal mask ----
            const int qrow0 = q0 + 16 * w + g;
            if (k0 + 63 > q0 + 16 * w) {
                #pragma unroll
                for (int j = 0; j < 8; j++) {
                    int kc = k0 + 8 * j + t2;
                    if (kc     > qrow0)     s[j][0] = -1e30f;
                    if (kc + 1 > qrow0)     s[j][1] = -1e30f;
                    if (kc     > qrow0 + 8) s[j][2] = -1e30f;
                    if (kc + 1 > qrow0 + 8) s[j][3] = -1e30f;
                }
            }

            // ---- online softmax ----
            float mx0 = -1e30f, mx1 = -1e30f;
            #pragma unroll
            for (int j = 0; j < 8; j++) {
                mx0 = fmaxf(mx0, fmaxf(s[j][0], s[j][1]));
                mx1 = fmaxf(mx1, fmaxf(s[j][2], s[j][3]));
            }
            mx0 = fmaxf(mx0, __shfl_xor_sync(0xffffffffu, mx0, 1));
            mx0 = fmaxf(mx0, __shfl_xor_sync(0xffffffffu, mx0, 2));
            mx1 = fmaxf(mx1, __shfl_xor_sync(0xffffffffu, mx1, 1));
            mx1 = fmaxf(mx1, __shfl_xor_sync(0xffffffffu, mx1, 2));
            float mn0 = fmaxf(mrow[0], mx0), mn1 = fmaxf(mrow[1], mx1);
            float corr0 = exp2p((mrow[0] - mn0) * cexp);
            float corr1 = exp2p((mrow[1] - mn1) * cexp);
            mrow[0] = mn0; mrow[1] = mn1;
            float nm0 = -mn0 * cexp, nm1 = -mn1 * cexp;

            float sum0 = 0.f, sum1 = 0.f;
            uint32_t pa[4][4];
            #pragma unroll
            for (int j = 0; j < 8; j++) {
                float p0 = exp2p(fmaf(s[j][0], cexp, nm0));
                float p1 = exp2p(fmaf(s[j][1], cexp, nm0));
                float p2 = exp2p(fmaf(s[j][2], cexp, nm1));
                float p3 = exp2p(fmaf(s[j][3], cexp, nm1));
                sum0 += p0 + p1; sum1 += p2 + p3;
                pa[j >> 1][(j & 1) * 2 + 0] = pack2h(p0, p1);
                pa[j >> 1][(j & 1) * 2 + 1] = pack2h(p2, p3);
            }
            sum0 += __shfl_xor_sync(0xffffffffu, sum0, 1);
            sum0 += __shfl_xor_sync(0xffffffffu, sum0, 2);
            sum1 += __shfl_xor_sync(0xffffffffu, sum1, 1);
            sum1 += __shfl_xor_sync(0xffffffffu, sum1, 2);
            lrow[0] = lrow[0] * corr0 + sum0;
            lrow[1] = lrow[1] * corr1 + sum1;
            #pragma unroll
            for (int j = 0; j < 8; j++) {
                o[j][0] *= corr0; o[j][1] *= corr0;
                o[j][2] *= corr1; o[j][3] *= corr1;
            }

            // ---- O += P * V^T ----
            #pragma unroll
            for (int ks = 0; ks < 4; ks++) {
                #pragma unroll
                for (int p = 0; p < 4; p++) {
                    uint32_t bd = st + OPB + (p * 16 + brow) * ROWB + (bkb + ks * 16) * 2;
                    uint32_t th[4];
                    LDMX4(th, bd);
                    MMA_F16(o[2*p],   pa[ks], th[0], th[1]);
                    MMA_F16(o[2*p+1], pa[ks], th[2], th[3]);
                }
            }
        }
        __syncthreads();
    }

    // ---- shaped epilogue: write g_AM fp16 ----
    const float rgv = RG[h], sgv = SG[h], cgv = CG[h];
    const float inv0 = 1.f / lrow[0], inv1 = 1.f / lrow[1];
    const int row0 = q0 + 16 * w + g;
    const size_t vbase = (size_t)bh * 2048 * 64;
    const size_t amr0 = (size_t)((bh >> 4) * 2048 + row0);
    const int colb = h * 64;
    const float s0c = rgv * inv0, s1c = rgv * inv1;
    #pragma unroll
    for (int j = 0; j < 8; j++) {
        int hd = 8 * j + t2;
        float2 v0  = *(const float2*)&g_v [vbase + (size_t)row0 * 64 + hd];
        float2 pm0 = *(const float2*)&g_pm[vbase + (size_t)row0 * 64 + hd];
        float r0 = fmaf(s0c, o[j][0], fmaf(sgv, v0.x, -cgv * pm0.x));
        float r1 = fmaf(s0c, o[j][1], fmaf(sgv, v0.y, -cgv * pm0.y));
        *(uint32_t*)(g_AM + amr0 * 1024 + colb + hd) = pack2h(r0, r1);

        float2 v1  = *(const float2*)&g_v [vbase + (size_t)(row0 + 8) * 64 + hd];
        float2 pm1 = *(const float2*)&g_pm[vbase + (size_t)(row0 + 8) * 64 + hd];
        float r2 = fmaf(s1c, o[j][2], fmaf(sgv, v1.x, -cgv * pm1.x));
        float r3 = fmaf(s1c, o[j][3], fmaf(sgv, v1.y, -cgv * pm1.y));
        *(uint32_t*)(g_AM + (amr0 + 8) * 1024 + colb + hd) = pack2h(r2, r3);
    }
}

// ---------------------------------------------------------------------------
extern "C" void kernel_launch(void* const* d_in, const int* in_sizes, int n_in,
                              void* d_out, int out_size)
{
    (void)in_sizes; (void)n_in; (void)out_size;
    const float* x      = (const float*)d_in[0];
    const float* qk_w   = (const float*)d_in[1];
    const float* qk_b   = (const float*)d_in[2];
    const float* v_w    = (const float*)d_in[3];
    const float* cprojw = (const float*)d_in[4];
    const float* rg     = (const float*)d_in[5];
    const float* sg     = (const float*)d_in[6];
    const float* cg     = (const float*)d_in[7];

    cudaFuncSetAttribute(mma_gemm, cudaFuncAttributeMaxDynamicSharedMemorySize, SMEM_GEMM);
    cudaFuncSetAttribute(attn_mma, cudaFuncAttributeMaxDynamicSharedMemorySize, ATTN_SMEM2);

    convert_A<<<2048, 256>>>(x);
    convert_W<<<dim3(64, 32), 256>>>(qk_w,   2048, 0, 0);
    convert_W<<<dim3(32, 32), 256>>>(v_w,    1024, 0, 2048);
    convert_W<<<dim3(32, 32), 256>>>(cprojw, 1024, 1, 0);
    mma_gemm<<<dim3(24, 32), 256, SMEM_GEMM>>>(0, qk_b, nullptr);
    convert_VT<<<dim3(64, 32), 256>>>();
    prefix_kernel<<<dim3(32, 2), 1024>>>();
    attn_mma<<<dim3(16, 32), 256, ATTN_SMEM2>>>(rg, sg, cg);
    mma_gemm<<<dim3(8, 32), 256, SMEM_GEMM>>>(1, nullptr, (float*)d_out);
}

// round 12
// speedup vs baseline: 5.6684x; 1.0267x over previous
#include <cuda_runtime.h>
#include <cuda_bf16.h>
#include <cuda_fp16.h>
#include <cstdint>

// Problem constants
#define BB  2
#define SS  2048
#define DD  1024
#define HH  16
#define HDD 64

typedef unsigned long long u64;

// ---------------------------------------------------------------------------
// Scratch (device globals; allocation-free rule)
// ---------------------------------------------------------------------------
__device__ float  g_v [BB*HH*SS*HDD];  // fp32 natural [bh][s][hd]
__device__ __half g_pm[BB*HH*SS*HDD];  // causal prefix-mean of v (fp16)

// fp16 operands (fp32 accumulate in MMA)
__device__ __half g_Q [BB*HH*SS*HDD];   // [bh][s][hd]
__device__ __half g_K [BB*HH*SS*HDD];   // [bh][s][hd]
__device__ __half g_VT[BB*HH*HDD*SS];   // [bh][hd][s]

__device__ __half g_XA[4096*1024];      // x row-major fp16
__device__ __half g_AM[4096*1024];      // attention out row-major fp16
__device__ __half g_WB[3072*1024];      // [n][k]: 0..2047 qk_w^T, 2048.. v_w^T
__device__ __half g_WC[1024*1024];      // cproj^T [n][k]

// ---------------------------------------------------------------------------
// PTX helpers
// ---------------------------------------------------------------------------
__device__ __forceinline__ uint32_t smem_u32(const void* p) {
    uint32_t a;
    asm("{ .reg .u64 t; cvta.to.shared.u64 t, %1; cvt.u32.u64 %0, t; }"
        : "=r"(a) : "l"(p));
    return a;
}

#define CP16(dst, src) \
    asm volatile("cp.async.cg.shared.global [%0], [%1], 16;" \
                 :: "r"(dst), "l"(src) : "memory")
#define CP_COMMIT() asm volatile("cp.async.commit_group;" ::: "memory")
#define CP_WAIT0()  asm volatile("cp.async.wait_group 0;" ::: "memory")

#define LDMX4(r, addr) \
    asm volatile("ldmatrix.sync.aligned.m8n8.x4.shared.b16 {%0,%1,%2,%3}, [%4];" \
                 : "=r"((r)[0]), "=r"((r)[1]), "=r"((r)[2]), "=r"((r)[3]) : "r"(addr))

#define MMA_F16(d, a, b0, b1) \
    asm volatile("mma.sync.aligned.m16n8k16.row.col.f32.f16.f16.f32 " \
                 "{%0,%1,%2,%3}, {%4,%5,%6,%7}, {%8,%9}, {%0,%1,%2,%3};" \
                 : "+f"((d)[0]), "+f"((d)[1]), "+f"((d)[2]), "+f"((d)[3]) \
                 : "r"((a)[0]), "r"((a)[1]), "r"((a)[2]), "r"((a)[3]), \
                   "r"(b0), "r"(b1))

__device__ __forceinline__ uint32_t pack2h(float v0, float v1) {
    __half2 h = __floats2half2_rn(v0, v1);
    return *reinterpret_cast<uint32_t*>(&h);
}

// Fast exp2 (t <= 0), FMA/ALU pipes only, ~2e-6 rel err.
__device__ __forceinline__ float exp2p(float t) {
    t = fmaxf(t, -126.f);
    float z  = t + 12582912.f;          // round-to-nearest integer trick
    float nf = z - 12582912.f;
    float f  = t - nf;
    float p  = 1.3333558146e-3f;
    p = fmaf(p, f, 9.6181291076e-3f);
    p = fmaf(p, f, 5.5504108665e-2f);
    p = fmaf(p, f, 2.4022650696e-1f);
    p = fmaf(p, f, 6.9314718056e-1f);
    p = fmaf(p, f, 1.0f);
    int ib = __float_as_int(z) << 23;   // == n<<23 (mod 2^32)
    return __int_as_float(__float_as_int(p) + ib);
}

// ---------------------------------------------------------------------------
// convert_wx: one launch does x->fp16 AND all 3 weight transposes.
// grid (192, 32): bx<64 qk_w, <96 v_w, <128 cproj_w, >=128 x elementwise.
// ---------------------------------------------------------------------------
__global__ __launch_bounds__(256)
void convert_wx(const float* __restrict__ x,  const float* __restrict__ qkw,
                const float* __restrict__ vw, const float* __restrict__ cw)
{
    const int bx = blockIdx.x, by = blockIdx.y;
    if (bx >= 128) {
        // x conversion: blk in [0, 2048)
        int blk = (bx - 128) * 32 + by;
        size_t base = ((size_t)blk * 256 + threadIdx.x) * 8;
        float4 a = *(const float4*)(x + base);
        float4 b = *(const float4*)(x + base + 4);
        float xs[8] = {a.x, a.y, a.z, a.w, b.x, b.y, b.z, b.w};
        union { __half h[8]; uint4 u; } ph;
        #pragma unroll
        for (int i = 0; i < 8; i++) ph.h[i] = __float2half_rn(xs[i]);
        *(uint4*)(g_XA + base) = ph.u;
        return;
    }
    // weight transpose: W [1024][N] -> [n][k] fp16
    const float* W; int N, roff, nb;
    __half* dst;
    if (bx < 64)      { W = qkw; N = 2048; roff = 0;    dst = g_WB; nb = bx; }
    else if (bx < 96) { W = vw;  N = 1024; roff = 2048; dst = g_WB; nb = bx - 64; }
    else              { W = cw;  N = 1024; roff = 0;    dst = g_WC; nb = bx - 96; }
    __shared__ float t[32][33];
    const int n0 = nb * 32, k0 = by * 32;
    const int tx = threadIdx.x & 31, ty = threadIdx.x >> 5;
    #pragma unroll
    for (int i = 0; i < 4; i++)
        t[ty + 8*i][tx] = W[(size_t)(k0 + ty + 8*i) * N + n0 + tx];
    __syncthreads();
    #pragma unroll
    for (int i = 0; i < 4; i++) {
        size_t off = (size_t)(roff + n0 + ty + 8*i) * 1024 + k0 + tx;
        dst[off] = __float2half_rn(t[tx][ty + 8*i]);
    }
}

// ---------------------------------------------------------------------------
// convert_VT: g_v [bh][s][hd] fp32 -> g_VT [bh][hd][s] fp16
// ---------------------------------------------------------------------------
__global__ __launch_bounds__(256)
void convert_VT()
{
    __shared__ float tb[32][65];
    const int bh = blockIdx.y, s0 = blockIdx.x * 32;
    const int tid = threadIdx.x;
    {
        int r = tid >> 3, c8 = (tid & 7) * 8;
        const float* vp = g_v + ((size_t)bh * 2048 + s0 + r) * 64 + c8;
        float4 a = *(const float4*)vp, b = *(const float4*)(vp + 4);
        tb[r][c8+0]=a.x; tb[r][c8+1]=a.y; tb[r][c8+2]=a.z; tb[r][c8+3]=a.w;
        tb[r][c8+4]=b.x; tb[r][c8+5]=b.y; tb[r][c8+6]=b.z; tb[r][c8+7]=b.w;
    }
    __syncthreads();
    int hd = tid >> 2, sg = (tid & 3) * 8;
    union { __half h[8]; uint4 u; } ph;
    #pragma unroll
    for (int i = 0; i < 8; i++)
        ph.h[i] = __float2half_rn(tb[sg + i][hd]);
    size_t off = ((size_t)bh * 64 + hd) * 2048 + s0 + sg;
    *(uint4*)(g_VT + off) = ph.u;
}

// ---------------------------------------------------------------------------
// mma.sync fp16 GEMM, persistent tiles.  C = A*B, fp32 accumulate.
// Tile 128x128, K=1024 in 64-chunks (16 iters), cp.async double buffer,
// 2 CTAs/SM, grid = 296 (exact occupancy fill).
// stage: A|B, each 128 rows x 144B = 18432B -> 36864B/stage.
// ---------------------------------------------------------------------------
#define SMEM_STAGE 36864
#define SMEM_GEMM  (2 * SMEM_STAGE)

__global__ __launch_bounds__(256, 2)
void mma_gemm(int mode, const float* __restrict__ QKB, float* __restrict__ OUT)
{
    extern __shared__ char smc[];
    const uint32_t sbase = smem_u32(smc);
    const int tid = threadIdx.x, lane = tid & 31, wid = tid >> 5;
    const int warpM = wid & 3, warpN = wid >> 2;

    const __half *As, *Bs;
    const int ntn = mode ? 8 : 24;
    if (mode == 0) { As = g_XA; Bs = g_WB; }
    else           { As = g_AM; Bs = g_WC; }
    const int total = ntn * 32;

    for (int tile = blockIdx.x; tile < total; tile += gridDim.x) {
        const int nt = tile % ntn, mt = tile / ntn;
        const int m0 = mt * 128, n0 = nt * 128;

        float c[16][4];
        #pragma unroll
        for (int i = 0; i < 16; i++)
            #pragma unroll
            for (int j = 0; j < 4; j++) c[i][j] = 0.f;

        // 2 arrays x 1024 16B-chunks = 2048 chunks, 8 per thread
        auto load_stage = [&](int it, int buf) {
            const uint32_t st = sbase + buf * SMEM_STAGE;
            const int k0 = it * 64;
            #pragma unroll
            for (int cc = 0; cc < 8; cc++) {
                int id  = cc * 256 + tid;
                int arr = id >> 10, rem = id & 1023, row = rem >> 3, kq = rem & 7;
                const __half* g = arr ? Bs : As;
                int grow = arr ? (n0 + row) : (m0 + row);
                CP16(st + arr * 18432 + row * 144 + kq * 16,
                     g + (size_t)grow * 1024 + k0 + kq * 8);
            }
            CP_COMMIT();
        };

        load_stage(0, 0);
        for (int it = 0; it < 16; it++) {
            CP_WAIT0();
            __syncthreads();
            if (it + 1 < 16) load_stage(it + 1, (it + 1) & 1);
            const uint32_t st = sbase + (it & 1) * SMEM_STAGE;

            const int matq = lane >> 3, r8 = lane & 7;
            #pragma unroll
            for (int kh = 0; kh < 4; kh++) {
                uint32_t ah[2][4];
                const int arow = ((matq & 1) << 3) + r8;
                const int akof = (((matq >> 1) << 3) + kh * 16) * 2;
                #pragma unroll
                for (int mt2 = 0; mt2 < 2; mt2++) {
                    int row = warpM * 32 + mt2 * 16 + arow;
                    LDMX4(ah[mt2], st + row * 144 + akof);
                }
                const int brow = ((matq >> 1) << 3) + r8;
                const int bkof = (((matq & 1) << 3) + kh * 16) * 2;
                #pragma unroll
                for (int p = 0; p < 4; p++) {
                    int row = warpN * 64 + p * 16 + brow;
                    uint32_t th[4];
                    LDMX4(th, st + 18432 + row * 144 + bkof);
                    #pragma unroll
                    for (int mt2 = 0; mt2 < 2; mt2++) {
                        MMA_F16(c[mt2*8 + 2*p],     ah[mt2], th[0], th[1]);
                        MMA_F16(c[mt2*8 + 2*p + 1], ah[mt2], th[2], th[3]);
                    }
                }
            }
            __syncthreads();
        }

        if (mode == 1) {
            #pragma unroll
            for (int mt2 = 0; mt2 < 2; mt2++)
                #pragma unroll
                for (int n2 = 0; n2 < 8; n2++) {
                    float* f = c[mt2*8+n2];
                    int r0 = m0 + warpM * 32 + mt2 * 16 + (lane >> 2);
                    int cb = n0 + warpN * 64 + n2 * 8 + (lane & 3) * 2;
                    *(float2*)&OUT[(size_t)r0 * 1024 + cb]       = make_float2(f[0], f[1]);
                    *(float2*)&OUT[(size_t)(r0 + 8) * 1024 + cb] = make_float2(f[2], f[3]);
                }
        } else {
            #pragma unroll
            for (int mt2 = 0; mt2 < 2; mt2++)
                #pragma unroll
                for (int n2 = 0; n2 < 8; n2++) {
                    float* f = c[mt2*8+n2];
                    int r0 = m0 + warpM * 32 + mt2 * 16 + (lane >> 2);
                    int cb = n0 + warpN * 64 + n2 * 8 + (lane & 3) * 2;
                    #pragma unroll
                    for (int rr = 0; rr < 2; rr++) {
                        int mm = r0 + rr * 8;
                        int bb = mm >> 11, ss = mm & 2047;
                        float v0 = f[rr*2], v1 = f[rr*2+1];
                        if (cb < 2048) {
                            v0 += QKB[cb]; v1 += QKB[cb+1];
                            int colg = cb & 1023, hh = colg >> 6, hd = colg & 63;
                            size_t off = ((size_t)(bb * 16 + hh) * 2048 + ss) * 64 + hd;
                            __half* dst = (cb < 1024) ? g_Q : g_K;
                            *(uint32_t*)(dst + off) = pack2h(v0, v1);
                        } else {
                            int colg = cb - 2048, hh = colg >> 6, hd = colg & 63;
                            *(float2*)&g_v[((size_t)(bb * 16 + hh) * 2048 + ss) * 64 + hd] =
                                make_float2(v0, v1);
                        }
                    }
                }
        }
        __syncthreads();   // c / smem reuse safety before next persistent tile
    }
}

// ---------------------------------------------------------------------------
// prefix mean of v: grid (32 bh, 2 hd-halves), block 1024 = 32 chunks x 32 hd
// writes fp16 pm
// ---------------------------------------------------------------------------
__global__ __launch_bounds__(1024)
void prefix_kernel()
{
    const int bh = blockIdx.x;
    const int hd = (blockIdx.y << 5) + (threadIdx.x & 31);
    const int c  = threadIdx.x >> 5;            // 0..31, chunk of 64 rows
    const float* vp = g_v  + (size_t)bh * SS * HDD;
    __half*      pp = g_pm + (size_t)bh * SS * HDD;
    __shared__ float cs[32][33];

    const int s0 = c * 64;
    float acc = 0.f;
    #pragma unroll 4
    for (int i = 0; i < 64; i++) acc += vp[(s0 + i) * 64 + hd];
    cs[c][threadIdx.x & 31] = acc;
    __syncthreads();

    float off = 0.f;
    for (int cc = 0; cc < c; cc++) off += cs[cc][threadIdx.x & 31];

    float run = off;
    #pragma unroll 4
    for (int i = 0; i < 64; i++) {
        int s = s0 + i;
        run += vp[s * 64 + hd];
        pp[s * 64 + hd] = __float2half_rn(run / (float)(s + 1));
    }
}

// ---------------------------------------------------------------------------
// Flash attention on mma.sync fp16, 2 CTAs/SM.
// Block: 128 q x (bh).  8 warps, 16 q-rows per warp.  kv tiles of 64.
// stage: K | VT, each 64 rows x 144B = 9216B -> 18432B/stage, 2 stages.
// ---------------------------------------------------------------------------
#define ROWB 144
#define OPB  (64 * ROWB)      // 9216
#define STAGEB (2 * OPB)      // 18432
#define ATTN_SMEM2 (2 * STAGEB)

__global__ __launch_bounds__(256, 2)
void attn_mma(const float* __restrict__ RG, const float* __restrict__ SG,
              const float* __restrict__ CG)
{
    extern __shared__ char smc[];
    const uint32_t sb = smem_u32(smc);
    const int tid = threadIdx.x, lane = tid & 31, w = tid >> 5;
    const int qt = (gridDim.x - 1) - blockIdx.x;
    const int bh = blockIdx.y, h = bh & 15;
    const int q0 = qt * 128;

    const __half* Qp = g_Q + (size_t)bh * 2048 * 64;
    const __half* Kp = g_K + (size_t)bh * 2048 * 64;
    const __half* VTp = g_VT + (size_t)bh * 64 * 2048;

    // ---- stage Q (128 rows x 128B, stride ROWB) into stage0 region ----
    #pragma unroll
    for (int cc = 0; cc < 4; cc++) {
        int id = cc * 256 + tid;            // 0..1023
        int row = id >> 3, kq = id & 7;
        const __half* src = Qp + (size_t)(q0 + row) * 64 + kq * 8;
        CP16(sb + row * ROWB + kq * 16, src);
    }
    CP_COMMIT(); CP_WAIT0();
    __syncthreads();

    // ---- extract persistent Q A-frags (4 ksteps) ----
    const int matq = lane >> 3, r8 = lane & 7;
    const int arow = ((matq & 1) << 3) + r8;
    const int akb  = ((matq >> 1) << 3);
    uint32_t qf[4][4];
    #pragma unroll
    for (int ks = 0; ks < 4; ks++)
        LDMX4(qf[ks], sb + (16 * w + arow) * ROWB + (akb + ks * 16) * 2);
    __syncthreads();   // Q staging free before KV loads overwrite it

    float o[8][4];
    #pragma unroll
    for (int j = 0; j < 8; j++)
        #pragma unroll
        for (int e = 0; e < 4; e++) o[j][e] = 0.f;
    float mrow[2] = { -1e30f, -1e30f }, lrow[2] = { 0.f, 0.f };

    const int ntiles = 2 * qt + 2;
    const int brow = ((matq >> 1) << 3) + r8;
    const int bkb  = ((matq & 1) << 3);
    const int g = lane >> 2, t2 = (lane & 3) * 2;
    const float cexp = 0.125f * 1.44269504f;

    // K | VT: 2 arrays x 512 chunks = 1024 chunks, 4 per thread
    auto load_kv = [&](int t, int buf) {
        const uint32_t st = sb + buf * STAGEB;
        const int k0 = t * 64;
        #pragma unroll
        for (int cc = 0; cc < 4; cc++) {
            int id = cc * 256 + tid;
            int arr = id >> 9, rem = id & 511, row = rem >> 3, kq = rem & 7;
            const __half* gp = arr ? (VTp + (size_t)row * 2048 + k0 + kq * 8)
                                   : (Kp + (size_t)(k0 + row) * 64 + kq * 8);
            CP16(st + arr * OPB + row * ROWB + kq * 16, gp);
        }
        CP_COMMIT();
    };

    load_kv(0, 0);
    for (int t = 0; t < ntiles; t++) {
        CP_WAIT0();
        __syncthreads();
        if (t + 1 < ntiles) load_kv(t + 1, (t + 1) & 1);
        const uint32_t st = sb + (t & 1) * STAGEB;
        const int k0 = t * 64;
        const bool active = (k0 <= q0 + 16 * w + 15);

        if (active) {
            // ---- S = Q K^T ----
            float s[8][4];
            #pragma unroll
            for (int j = 0; j < 8; j++)
                #pragma unroll
                for (int e = 0; e < 4; e++) s[j][e] = 0.f;

            #pragma unroll
            for (int ks = 0; ks < 4; ks++) {
                #pragma unroll
                for (int p = 0; p < 4; p++) {
                    uint32_t bd = st + (p * 16 + brow) * ROWB + (bkb + ks * 16) * 2;
                    uint32_t th[4];
                    LDMX4(th, bd);
                    MMA_F16(s[2*p],   qf[ks], th[0], th[1]);
                    MMA_F16(s[2*p+1], qf[ks], th[2], th[3]);
                }
            }

            // ---- causal mask ----
            const int qrow0 = q0 + 16 * w + g;
            if (k0 + 63 > q0 + 16 * w) {
                #pragma unroll
                for (int j = 0; j < 8; j++) {
                    int kc = k0 + 8 * j + t2;
                    if (kc     > qrow0)     s[j][0] = -1e30f;
                    if (kc + 1 > qrow0)     s[j][1] = -1e30f;
                    if (kc     > qrow0 + 8) s[j][2] = -1e30f;
                    if (kc + 1 > qrow0 + 8) s[j][3] = -1e30f;
                }
            }

            // ---- online softmax ----
            float mx0 = -1e30f, mx1 = -1e30f;
            #pragma unroll
            for (int j = 0; j < 8; j++) {
                mx0 = fmaxf(mx0, fmaxf(s[j][0], s[j][1]));
                mx1 = fmaxf(mx1, fmaxf(s[j][2], s[j][3]));
            }
            mx0 = fmaxf(mx0, __shfl_xor_sync(0xffffffffu, mx0, 1));
            mx0 = fmaxf(mx0, __shfl_xor_sync(0xffffffffu, mx0, 2));
            mx1 = fmaxf(mx1, __shfl_xor_sync(0xffffffffu, mx1, 1));
            mx1 = fmaxf(mx1, __shfl_xor_sync(0xffffffffu, mx1, 2));
            float mn0 = fmaxf(mrow[0], mx0), mn1 = fmaxf(mrow[1], mx1);
            float corr0 = exp2p((mrow[0] - mn0) * cexp);
            float corr1 = exp2p((mrow[1] - mn1) * cexp);
            mrow[0] = mn0; mrow[1] = mn1;
            float nm0 = -mn0 * cexp, nm1 = -mn1 * cexp;

            float sum0 = 0.f, sum1 = 0.f;
            uint32_t pa[4][4];
            #pragma unroll
            for (int j = 0; j < 8; j++) {
                float p0 = exp2p(fmaf(s[j][0], cexp, nm0));
                float p1 = exp2p(fmaf(s[j][1], cexp, nm0));
                float p2 = exp2p(fmaf(s[j][2], cexp, nm1));
                float p3 = exp2p(fmaf(s[j][3], cexp, nm1));
                sum0 += p0 + p1; sum1 += p2 + p3;
                pa[j >> 1][(j & 1) * 2 + 0] = pack2h(p0, p1);
                pa[j >> 1][(j & 1) * 2 + 1] = pack2h(p2, p3);
            }
            sum0 += __shfl_xor_sync(0xffffffffu, sum0, 1);
            sum0 += __shfl_xor_sync(0xffffffffu, sum0, 2);
            sum1 += __shfl_xor_sync(0xffffffffu, sum1, 1);
            sum1 += __shfl_xor_sync(0xffffffffu, sum1, 2);
            lrow[0] = lrow[0] * corr0 + sum0;
            lrow[1] = lrow[1] * corr1 + sum1;
            #pragma unroll
            for (int j = 0; j < 8; j++) {
                o[j][0] *= corr0; o[j][1] *= corr0;
                o[j][2] *= corr1; o[j][3] *= corr1;
            }

            // ---- O += P * V^T ----
            #pragma unroll
            for (int ks = 0; ks < 4; ks++) {
                #pragma unroll
                for (int p = 0; p < 4; p++) {
                    uint32_t bd = st + OPB + (p * 16 + brow) * ROWB + (bkb + ks * 16) * 2;
                    uint32_t th[4];
                    LDMX4(th, bd);
                    MMA_F16(o[2*p],   pa[ks], th[0], th[1]);
                    MMA_F16(o[2*p+1], pa[ks], th[2], th[3]);
                }
            }
        }
        __syncthreads();
    }

    // ---- shaped epilogue: write g_AM fp16 ----
    const float rgv = RG[h], sgv = SG[h], cgv = CG[h];
    const float inv0 = 1.f / lrow[0], inv1 = 1.f / lrow[1];
    const int row0 = q0 + 16 * w + g;
    const size_t vbase = (size_t)bh * 2048 * 64;
    const size_t amr0 = (size_t)((bh >> 4) * 2048 + row0);
    const int colb = h * 64;
    const float s0c = rgv * inv0, s1c = rgv * inv1;
    #pragma unroll
    for (int j = 0; j < 8; j++) {
        int hd = 8 * j + t2;
        float2 v0 = *(const float2*)&g_v[vbase + (size_t)row0 * 64 + hd];
        float2 pm0 = __half22float2(*(const __half2*)&g_pm[vbase + (size_t)row0 * 64 + hd]);
        float r0 = fmaf(s0c, o[j][0], fmaf(sgv, v0.x, -cgv * pm0.x));
        float r1 = fmaf(s0c, o[j][1], fmaf(sgv, v0.y, -cgv * pm0.y));
        *(uint32_t*)(g_AM + amr0 * 1024 + colb + hd) = pack2h(r0, r1);

        float2 v1 = *(const float2*)&g_v[vbase + (size_t)(row0 + 8) * 64 + hd];
        float2 pm1 = __half22float2(*(const __half2*)&g_pm[vbase + (size_t)(row0 + 8) * 64 + hd]);
        float r2 = fmaf(s1c, o[j][2], fmaf(sgv, v1.x, -cgv * pm1.x));
        float r3 = fmaf(s1c, o[j][3], fmaf(sgv, v1.y, -cgv * pm1.y));
        *(uint32_t*)(g_AM + (amr0 + 8) * 1024 + colb + hd) = pack2h(r2, r3);
    }
}

// ---------------------------------------------------------------------------
extern "C" void kernel_launch(void* const* d_in, const int* in_sizes, int n_in,
                              void* d_out, int out_size)
{
    (void)in_sizes; (void)n_in; (void)out_size;
    const float* x      = (const float*)d_in[0];
    const float* qk_w   = (const float*)d_in[1];
    const float* qk_b   = (const float*)d_in[2];
    const float* v_w    = (const float*)d_in[3];
    const float* cprojw = (const float*)d_in[4];
    const float* rg     = (const float*)d_in[5];
    const float* sg     = (const float*)d_in[6];
    const float* cg     = (const float*)d_in[7];

    cudaFuncSetAttribute(mma_gemm, cudaFuncAttributeMaxDynamicSharedMemorySize, SMEM_GEMM);
    cudaFuncSetAttribute(attn_mma, cudaFuncAttributeMaxDynamicSharedMemorySize, ATTN_SMEM2);

    convert_wx<<<dim3(192, 32), 256>>>(x, qk_w, v_w, cprojw);
    mma_gemm<<<296, 256, SMEM_GEMM>>>(0, qk_b, nullptr);
    convert_VT<<<dim3(64, 32), 256>>>();
    prefix_kernel<<<dim3(32, 2), 1024>>>();
    attn_mma<<<dim3(16, 32), 256, ATTN_SMEM2>>>(rg, sg, cg);
    mma_gemm<<<256, 256, SMEM_GEMM>>>(1, nullptr, (float*)d_out);
}